// round 15
// baseline (speedup 1.0000x reference)
#include <cuda_runtime.h>
#include <cuda_bf16.h>
#include <cstdint>
#include <math.h>

#define Nn 10000
#define Ee 160000
#define Gg 100
#define Ll 5
#define NT 1250   // 128-edge tiles

typedef unsigned long long u64;
typedef unsigned short ush;

__device__ float g_feat [Nn*128];
__device__ float g_featA[Nn*128];
__device__ float g_featB[Nn*128];
__device__ float g_sh   [Nn*9];
__device__ float g_pos  [Nn*3];
__device__ float g_msum [Nn*128];
__device__ float g_psum [Nn*3];
__device__ float g_ssum [Nn*9];
__device__ float g_deg  [Nn];
__device__ float g_com  [Gg*3];
__device__ float g_cnt  [Gg];
__device__ float g_P1   [10*128];
__device__ float g_P2   [10*128];
__device__ float g_cmsg [10];
__device__ float g_pool [Gg*140];
__device__ int   g_off  [Nn];
__device__ int   g_cursor[Nn];
__device__ int   g_er   [Ee];
__device__ int   g_ec   [Ee];
__device__ ush   g_Wbh [40*17408];          // [l*8+slot][n*136+k] hi
__device__ ush   g_Wbl [40*17408];          // lo

__device__ __forceinline__ float silu_f(float x) { return x / (1.0f + __expf(-x)); }

__device__ __forceinline__ void sph2(float vx, float vy, float vz, float* o) {
    const float S3 = 1.7320508075688772f, HS3 = 0.8660254037844386f;
    float r = sqrtf(vx*vx + vy*vy + vz*vz);
    float inv = 1.0f / fmaxf(r, 1e-12f);
    float x = vx*inv, y = vy*inv, z = vz*inv;
    o[0] = S3*x*z; o[1] = S3*x*y; o[2] = y*y - 0.5f*(x*x + z*z);
    o[3] = S3*y*z; o[4] = HS3*(z*z - x*x);
}

// ---- HMMA helpers ----
__device__ __forceinline__ unsigned smem_u32(const void* p) {
    unsigned a; asm("{ .reg .u64 t; cvta.to.shared.u64 t, %1; cvt.u32.u64 %0, t; }" : "=r"(a) : "l"(p));
    return a;
}
__device__ __forceinline__ void ldsm4(unsigned addr, unsigned* r) {
    asm volatile("ldmatrix.sync.aligned.m8n8.x4.shared.b16 {%0,%1,%2,%3}, [%4];"
        : "=r"(r[0]), "=r"(r[1]), "=r"(r[2]), "=r"(r[3]) : "r"(addr));
}
__device__ __forceinline__ void mma_bf16(float* d, const unsigned* a, unsigned b0, unsigned b1) {
    asm volatile("mma.sync.aligned.m16n8k16.row.col.f32.bf16.bf16.f32 "
        "{%0,%1,%2,%3},{%4,%5,%6,%7},{%8,%9},{%0,%1,%2,%3};"
        : "+f"(d[0]), "+f"(d[1]), "+f"(d[2]), "+f"(d[3])
        : "r"(a[0]), "r"(a[1]), "r"(a[2]), "r"(a[3]), "r"(b0), "r"(b1));
}
__device__ __forceinline__ void split_bf16(float v, unsigned& h, unsigned& l) {
    __nv_bfloat16 hb = __float2bfloat16(v);
    h = (unsigned)__bfloat16_as_ushort(hb);
    l = (unsigned)__bfloat16_as_ushort(__float2bfloat16(v - __bfloat162float(hb)));
}

// ---- old 16x64 core (nodeup/featab, proven) ----
__device__ __forceinline__ void hmma_gemm(unsigned aH, unsigned aL, unsigned bH, unsigned bL,
                                          int m0, int n0, int lane, float acc[8][4]) {
    unsigned aoff = (unsigned)((m0 + (lane & 15))*272 + (lane >> 4)*16);
    unsigned boff = (unsigned)((n0 + (lane & 15))*272 + (lane >> 4)*16);
    #pragma unroll
    for (int kk = 0; kk < 8; kk++) {
        unsigned kb = kk*32;
        unsigned Ah[4], Al[4];
        ldsm4(aH + aoff + kb, Ah);
        ldsm4(aL + aoff + kb, Al);
        #pragma unroll
        for (int t = 0; t < 4; t++) {
            unsigned bo = boff + t*16*272 + kb;
            unsigned Bh[4], Bl[4];
            ldsm4(bH + bo, Bh);
            ldsm4(bL + bo, Bl);
            mma_bf16(acc[2*t],   Ah, Bh[0], Bh[2]);
            mma_bf16(acc[2*t],   Ah, Bl[0], Bl[2]);
            mma_bf16(acc[2*t],   Al, Bh[0], Bh[2]);
            mma_bf16(acc[2*t+1], Ah, Bh[1], Bh[3]);
            mma_bf16(acc[2*t+1], Ah, Bl[1], Bl[3]);
            mma_bf16(acc[2*t+1], Al, Bh[1], Bh[3]);
        }
    }
}

// ---- new 32x32 core (edge kernel) ----
__device__ __forceinline__ void hmma_g32(unsigned aH, unsigned aL, unsigned bH, unsigned bL,
                                         int m0, int n0, int lane, float acc[2][4][4]) {
    unsigned a0 = (unsigned)((m0 + (lane & 15))*272 + (lane >> 4)*16);
    unsigned b0 = (unsigned)((n0 + (lane & 15))*272 + (lane >> 4)*16);
    #pragma unroll
    for (int kk = 0; kk < 8; kk++) {
        unsigned kb = kk*32;
        unsigned Ah[2][4], Al[2][4];
        ldsm4(aH + a0 + kb, Ah[0]);
        ldsm4(aH + a0 + 16*272 + kb, Ah[1]);
        ldsm4(aL + a0 + kb, Al[0]);
        ldsm4(aL + a0 + 16*272 + kb, Al[1]);
        #pragma unroll
        for (int np = 0; np < 2; np++) {
            unsigned Bh[4], Bl[4];
            ldsm4(bH + b0 + np*16*272 + kb, Bh);
            ldsm4(bL + b0 + np*16*272 + kb, Bl);
            #pragma unroll
            for (int mf = 0; mf < 2; mf++) {
                mma_bf16(acc[mf][np*2],   Ah[mf], Bh[0], Bh[2]);
                mma_bf16(acc[mf][np*2],   Ah[mf], Bl[0], Bl[2]);
                mma_bf16(acc[mf][np*2],   Al[mf], Bh[0], Bh[2]);
                mma_bf16(acc[mf][np*2+1], Ah[mf], Bh[1], Bh[3]);
                mma_bf16(acc[mf][np*2+1], Ah[mf], Bl[1], Bl[3]);
                mma_bf16(acc[mf][np*2+1], Al[mf], Bh[1], Bh[3]);
            }
        }
    }
}

// fused dual-B core: same A, two weight pairs (p, s)
__device__ __forceinline__ void hmma_g32x2(unsigned aH, unsigned aL,
                                           unsigned pH, unsigned pL,
                                           unsigned sH, unsigned sL,
                                           int m0, int n0, int lane,
                                           float accp[2][4][4], float accs[2][4][4]) {
    unsigned a0 = (unsigned)((m0 + (lane & 15))*272 + (lane >> 4)*16);
    unsigned b0 = (unsigned)((n0 + (lane & 15))*272 + (lane >> 4)*16);
    #pragma unroll
    for (int kk = 0; kk < 8; kk++) {
        unsigned kb = kk*32;
        unsigned Ah[2][4], Al[2][4];
        ldsm4(aH + a0 + kb, Ah[0]);
        ldsm4(aH + a0 + 16*272 + kb, Ah[1]);
        ldsm4(aL + a0 + kb, Al[0]);
        ldsm4(aL + a0 + 16*272 + kb, Al[1]);
        #pragma unroll
        for (int np = 0; np < 2; np++) {
            unsigned Bh[4], Bl[4];
            ldsm4(pH + b0 + np*16*272 + kb, Bh);
            ldsm4(pL + b0 + np*16*272 + kb, Bl);
            #pragma unroll
            for (int mf = 0; mf < 2; mf++) {
                mma_bf16(accp[mf][np*2],   Ah[mf], Bh[0], Bh[2]);
                mma_bf16(accp[mf][np*2],   Ah[mf], Bl[0], Bl[2]);
                mma_bf16(accp[mf][np*2],   Al[mf], Bh[0], Bh[2]);
                mma_bf16(accp[mf][np*2+1], Ah[mf], Bh[1], Bh[3]);
                mma_bf16(accp[mf][np*2+1], Ah[mf], Bl[1], Bl[3]);
                mma_bf16(accp[mf][np*2+1], Al[mf], Bh[1], Bh[3]);
            }
            ldsm4(sH + b0 + np*16*272 + kb, Bh);
            ldsm4(sL + b0 + np*16*272 + kb, Bl);
            #pragma unroll
            for (int mf = 0; mf < 2; mf++) {
                mma_bf16(accs[mf][np*2],   Ah[mf], Bh[0], Bh[2]);
                mma_bf16(accs[mf][np*2],   Ah[mf], Bl[0], Bl[2]);
                mma_bf16(accs[mf][np*2],   Al[mf], Bh[0], Bh[2]);
                mma_bf16(accs[mf][np*2+1], Ah[mf], Bh[1], Bh[3]);
                mma_bf16(accs[mf][np*2+1], Ah[mf], Bl[1], Bl[3]);
                mma_bf16(accs[mf][np*2+1], Al[mf], Bh[1], Bh[3]);
            }
        }
    }
}

// weights -> split-bf16 [n][k] stride-136 tiles
// slot: 0 Wm2, 1 Wp1, 2 Ws1, 3 Wa, 4 Wb, 5 W5, 6 W6, 7 W7
__global__ void wprep_kernel(const float* __restrict__ Wm2, const float* __restrict__ Wp1,
                             const float* __restrict__ Ws1, const float* __restrict__ Wm1,
                             const float* __restrict__ Wn1, const float* __restrict__ Wn2) {
    int bid = blockIdx.x, l = bid >> 3, slot = bid & 7;
    const float* src;
    switch (slot) {
        case 0: src = Wm2 + (size_t)l*16384;              break;
        case 1: src = Wp1 + (size_t)l*16384;              break;
        case 2: src = Ws1 + (size_t)l*16384;              break;
        case 3: src = Wm1 + (size_t)l*260*128;            break;
        case 4: src = Wm1 + ((size_t)l*260 + 128)*128;    break;
        case 5: src = Wn1 + (size_t)l*256*128;            break;
        case 6: src = Wn1 + ((size_t)l*256 + 128)*128;    break;
        default:src = Wn2 + (size_t)l*16384;              break;
    }
    ush* dh = g_Wbh + (size_t)bid*17408;
    ush* dl = g_Wbl + (size_t)bid*17408;
    for (int o = threadIdx.x; o < 16384; o += 256) {
        int k = o >> 7, n = o & 127;
        unsigned h, lo;
        split_bf16(src[k*128 + n], h, lo);
        dh[n*136 + k] = (ush)h;
        dl[n*136 + k] = (ush)lo;
    }
}

// ---- init kernels ----
__global__ void node_init_kernel(const int* __restrict__ atoms, const float* __restrict__ emb) {
    int idx = blockIdx.x*256 + threadIdx.x;
    g_feat[idx] = emb[atoms[idx >> 7]*128 + (idx & 127)];
}
__global__ void com_kernel(const int* __restrict__ batch) {
    int i = blockIdx.x*256 + threadIdx.x;
    if (i >= Nn) return;
    int b = batch[i];
    atomicAdd(&g_com[b*3+0], g_pos[i*3+0]);
    atomicAdd(&g_com[b*3+1], g_pos[i*3+1]);
    atomicAdd(&g_com[b*3+2], g_pos[i*3+2]);
    atomicAdd(&g_cnt[b], 1.0f);
}
__global__ void deg_kernel(const int* __restrict__ ei) {
    int e = blockIdx.x*256 + threadIdx.x;
    if (e < Ee) atomicAdd(&g_deg[ei[e]], 1.0f);
}
__global__ void scan_kernel() {
    __shared__ int part[256];
    int tid = threadIdx.x;
    int lo = tid*40, hi = (lo + 40 < Nn) ? lo + 40 : Nn;
    int s = 0;
    for (int i = lo; i < hi; i++) s += (int)g_deg[i];
    part[tid] = s;
    __syncthreads();
    for (int off = 1; off < 256; off <<= 1) {
        int v = part[tid] + ((tid >= off) ? part[tid - off] : 0);
        __syncthreads(); part[tid] = v; __syncthreads();
    }
    int base = (tid > 0) ? part[tid - 1] : 0;
    for (int i = lo; i < hi; i++) { g_off[i] = base; base += (int)g_deg[i]; }
}
__global__ void sortscatter_kernel(const int* __restrict__ ei) {
    int e = blockIdx.x*256 + threadIdx.x;
    if (e >= Ee) return;
    int r = ei[e], c = ei[Ee + e];
    int p = g_off[r] + atomicAdd(&g_cursor[r], 1);
    g_er[p] = r; g_ec[p] = c;
}
__global__ void vocab_kernel(const float* __restrict__ emb, const float* __restrict__ Wsi1,
                             const float* __restrict__ WsiC1, const float* __restrict__ bsiC1,
                             const float* __restrict__ WsiC2, const float* __restrict__ bsiC2) {
    __shared__ float es[128], redv[128];
    int v = blockIdx.x, j = threadIdx.x;
    es[j] = emb[v*128 + j];
    __syncthreads();
    float p1 = 0.f, p2 = 0.f, hc = 0.f;
    for (int k = 0; k < 128; k++) {
        float e = es[k];
        p1 = fmaf(e, Wsi1[(1 + k)*128 + j], p1);
        p2 = fmaf(e, Wsi1[(129 + k)*128 + j], p2);
        hc = fmaf(e, WsiC1[k*128 + j], hc);
    }
    g_P1[v*128 + j] = p1; g_P2[v*128 + j] = p2;
    redv[j] = silu_f(hc + bsiC1[j]) * WsiC2[j*3 + 2];
    __syncthreads();
    for (int s = 64; s > 0; s >>= 1) {
        if (j < s) redv[j] += redv[j + s];
        __syncthreads();
    }
    if (j == 0) g_cmsg[v] = redv[0] + bsiC2[2];
}
__global__ void edge_init_kernel(const int* __restrict__ atoms,
                                 const float* __restrict__ Wsi1, const float* __restrict__ bsi1,
                                 const float* __restrict__ Wsi2, const float* __restrict__ bsi2) {
    int e = blockIdx.x*8 + (threadIdx.x >> 5);
    int lane = threadIdx.x & 31;
    int r = g_er[e], c = g_ec[e];
    float dp0 = g_pos[r*3+0] - g_pos[c*3+0];
    float dp1 = g_pos[r*3+1] - g_pos[c*3+1];
    float dp2 = g_pos[r*3+2] - g_pos[c*3+2];
    float dist = sqrtf(dp0*dp0 + dp1*dp1 + dp2*dp2);
    int ar = atoms[r], ac = atoms[c];
    float partial = 0.f;
    #pragma unroll
    for (int q = 0; q < 4; q++) {
        int d = lane + q*32;
        partial = fmaf(silu_f(dist*Wsi1[d] + g_P1[ar*128 + d] + g_P2[ac*128 + d] + bsi1[d]),
                       Wsi2[d*3 + 2], partial);
    }
    #pragma unroll
    for (int off = 16; off > 0; off >>= 1)
        partial += __shfl_xor_sync(0xffffffffu, partial, off);
    if (lane == 0) {
        float msg2 = partial + bsi2[2];
        float y2[5];
        sph2(dp0, dp1, dp2, y2);
        #pragma unroll
        for (int q = 0; q < 5; q++)
            atomicAdd(&g_ssum[r*9 + 4 + q], y2[q]*msg2);
    }
}
__global__ void sh_init_kernel(const int* __restrict__ atoms, const int* __restrict__ batch) {
    int i = blockIdx.x*256 + threadIdx.x;
    if (i >= Nn) return;
    float dg = fmaxf(g_deg[i], 1.0f);
    int b = batch[i];
    float cn = fmaxf(g_cnt[b], 1.0f);
    float y2[5];
    sph2(g_pos[i*3+0] - g_com[b*3+0]/cn, g_pos[i*3+1] - g_com[b*3+1]/cn,
         g_pos[i*3+2] - g_com[b*3+2]/cn, y2);
    float cm = g_cmsg[atoms[i]];
    #pragma unroll
    for (int q = 0; q < 4; q++) g_sh[i*9 + q] = 0.0f;
    #pragma unroll
    for (int q = 0; q < 5; q++)
        g_sh[i*9 + 4 + q] = g_ssum[i*9 + 4 + q]/dg + cm*y2[q];
    #pragma unroll
    for (int q = 0; q < 9; q++) g_ssum[i*9 + q] = 0.0f;
}

// ============ featAB via HMMA (layer 0 only, proven) ============
#define FABM_SMEM 208896
__global__ void __launch_bounds__(512, 1)
featab_mma(int layer) {
    extern __shared__ char smc[];
    unsigned sb = smem_u32(smc);
    int tid = threadIdx.x, w = tid >> 5, lane = tid & 31;
    int row0 = blockIdx.x * 128;

    {
        const uint4* ah = (const uint4*)(g_Wbh + (size_t)(layer*8 + 3)*17408);
        const uint4* al = (const uint4*)(g_Wbl + (size_t)(layer*8 + 3)*17408);
        const uint4* bh = (const uint4*)(g_Wbh + (size_t)(layer*8 + 4)*17408);
        const uint4* bl = (const uint4*)(g_Wbl + (size_t)(layer*8 + 4)*17408);
        uint4* dah = (uint4*)(smc + 69632);
        uint4* dal = (uint4*)(smc + 104448);
        uint4* dbh = (uint4*)(smc + 139264);
        uint4* dbl = (uint4*)(smc + 174080);
        for (int i = tid; i < 2176; i += 512) {
            dah[i] = ah[i]; dal[i] = al[i]; dbh[i] = bh[i]; dbl[i] = bl[i];
        }
    }
    #pragma unroll
    for (int q = 0; q < 8; q++) {
        int idx = tid + q*512;
        int r = idx >> 5, c4 = (idx & 31)*4;
        float4 v = make_float4(0.f,0.f,0.f,0.f);
        if (row0 + r < Nn) v = *(const float4*)(g_feat + (size_t)(row0 + r)*128 + c4);
        unsigned h[4], l[4];
        split_bf16(v.x, h[0], l[0]); split_bf16(v.y, h[1], l[1]);
        split_bf16(v.z, h[2], l[2]); split_bf16(v.w, h[3], l[3]);
        unsigned off = (unsigned)(r*136 + c4)*2u;
        *(uint2*)(smc + off)         = make_uint2(h[0]|(h[1]<<16), h[2]|(h[3]<<16));
        *(uint2*)(smc + 34816 + off) = make_uint2(l[0]|(l[1]<<16), l[2]|(l[3]<<16));
    }
    __syncthreads();

    int m0 = (w & 7)*16, n0 = (w >> 3)*64;
    int rl = m0 + (lane >> 2);
    float acc[8][4];
    #pragma unroll
    for (int i = 0; i < 8; i++)
        #pragma unroll
        for (int j = 0; j < 4; j++) acc[i][j] = 0.f;
    hmma_gemm(sb, sb + 34816, sb + 69632, sb + 104448, m0, n0, lane, acc);
    #pragma unroll
    for (int s = 0; s < 8; s++) {
        int col = n0 + s*8 + (lane & 3)*2;
        int ra = row0 + rl, rb = ra + 8;
        if (ra < Nn) *(float2*)(g_featA + (size_t)ra*128 + col) = make_float2(acc[s][0], acc[s][1]);
        if (rb < Nn) *(float2*)(g_featA + (size_t)rb*128 + col) = make_float2(acc[s][2], acc[s][3]);
    }
    #pragma unroll
    for (int i = 0; i < 8; i++)
        #pragma unroll
        for (int j = 0; j < 4; j++) acc[i][j] = 0.f;
    hmma_gemm(sb, sb + 34816, sb + 139264, sb + 174080, m0, n0, lane, acc);
    #pragma unroll
    for (int s = 0; s < 8; s++) {
        int col = n0 + s*8 + (lane & 3)*2;
        int ra = row0 + rl, rb = ra + 8;
        if (ra < Nn) *(float2*)(g_featB + (size_t)ra*128 + col) = make_float2(acc[s][0], acc[s][1]);
        if (rb < Nn) *(float2*)(g_featB + (size_t)rb*128 + col) = make_float2(acc[s][2], acc[s][3]);
    }
}

// ============ node update via HMMA + fused featAB for next layer (proven) ============
#define NUM_SMEM 209920
__global__ void __launch_bounds__(512, 1)
nodeup_mma(const float* __restrict__ b1, const float* __restrict__ b2, int layer, int next) {
    extern __shared__ char smc[];
    unsigned sb = smem_u32(smc);
    float* bb = (float*)(smc + 208896);
    int tid = threadIdx.x, w = tid >> 5, lane = tid & 31;
    int row0 = blockIdx.x * 128;

    {
        const uint4* ah = (const uint4*)(g_Wbh + (size_t)(layer*8 + 5)*17408);
        const uint4* al = (const uint4*)(g_Wbl + (size_t)(layer*8 + 5)*17408);
        const uint4* bh = (const uint4*)(g_Wbh + (size_t)(layer*8 + 6)*17408);
        const uint4* bl = (const uint4*)(g_Wbl + (size_t)(layer*8 + 6)*17408);
        uint4* d1h = (uint4*)(smc + 69632);
        uint4* d1l = (uint4*)(smc + 104448);
        uint4* d2h = (uint4*)(smc + 139264);
        uint4* d2l = (uint4*)(smc + 174080);
        for (int i = tid; i < 2176; i += 512) {
            d1h[i] = ah[i]; d1l[i] = al[i]; d2h[i] = bh[i]; d2l[i] = bl[i];
        }
    }
    if (tid < 128) { bb[tid] = b1[tid]; bb[128 + tid] = b2[tid]; }
    #pragma unroll
    for (int q = 0; q < 8; q++) {
        int idx = tid + q*512;
        int r = idx >> 5, c4 = (idx & 31)*4;
        float4 v = make_float4(0.f,0.f,0.f,0.f);
        if (row0 + r < Nn) v = *(const float4*)(g_feat + (size_t)(row0 + r)*128 + c4);
        unsigned h[4], l[4];
        split_bf16(v.x, h[0], l[0]); split_bf16(v.y, h[1], l[1]);
        split_bf16(v.z, h[2], l[2]); split_bf16(v.w, h[3], l[3]);
        unsigned off = (unsigned)(r*136 + c4)*2u;
        *(uint2*)(smc + off)         = make_uint2(h[0]|(h[1]<<16), h[2]|(h[3]<<16));
        *(uint2*)(smc + 34816 + off) = make_uint2(l[0]|(l[1]<<16), l[2]|(l[3]<<16));
    }
    __syncthreads();

    int m0 = (w & 7)*16, n0 = (w >> 3)*64;
    int rl = m0 + (lane >> 2);
    float acc[8][4];
    #pragma unroll
    for (int i = 0; i < 8; i++)
        #pragma unroll
        for (int j = 0; j < 4; j++) acc[i][j] = 0.f;
    hmma_gemm(sb, sb + 34816, sb + 69632, sb + 104448, m0, n0, lane, acc);
    __syncthreads();

    {
        const uint4* ah = (const uint4*)(g_Wbh + (size_t)(layer*8 + 7)*17408);
        const uint4* al = (const uint4*)(g_Wbl + (size_t)(layer*8 + 7)*17408);
        uint4* d1h = (uint4*)(smc + 69632);
        uint4* d1l = (uint4*)(smc + 104448);
        for (int i = tid; i < 2176; i += 512) { d1h[i] = ah[i]; d1l[i] = al[i]; }
    }
    #pragma unroll
    for (int q = 0; q < 8; q++) {
        int idx = tid + q*512;
        int r = idx >> 5, c4 = (idx & 31)*4;
        float4 v = make_float4(0.f,0.f,0.f,0.f);
        if (row0 + r < Nn) {
            float* mp = g_msum + (size_t)(row0 + r)*128 + c4;
            v = *(const float4*)mp;
            *(float4*)mp = make_float4(0.f,0.f,0.f,0.f);
            float inv = 1.0f / fmaxf(g_deg[row0 + r], 1.0f);
            v.x *= inv; v.y *= inv; v.z *= inv; v.w *= inv;
        }
        unsigned h[4], l[4];
        split_bf16(v.x, h[0], l[0]); split_bf16(v.y, h[1], l[1]);
        split_bf16(v.z, h[2], l[2]); split_bf16(v.w, h[3], l[3]);
        unsigned off = (unsigned)(r*136 + c4)*2u;
        *(uint2*)(smc + off)         = make_uint2(h[0]|(h[1]<<16), h[2]|(h[3]<<16));
        *(uint2*)(smc + 34816 + off) = make_uint2(l[0]|(l[1]<<16), l[2]|(l[3]<<16));
    }
    __syncthreads();
    hmma_gemm(sb, sb + 34816, sb + 139264, sb + 174080, m0, n0, lane, acc);
    __syncthreads();

    #pragma unroll
    for (int s = 0; s < 8; s++) {
        int col = n0 + s*8 + (lane & 3)*2;
        float v00 = silu_f(acc[s][0] + bb[col]);
        float v01 = silu_f(acc[s][1] + bb[col+1]);
        float v10 = silu_f(acc[s][2] + bb[col]);
        float v11 = silu_f(acc[s][3] + bb[col+1]);
        unsigned h0, l0, h1, l1;
        split_bf16(v00, h0, l0); split_bf16(v01, h1, l1);
        *(unsigned*)(smc + (rl*136 + col)*2)         = h0 | (h1 << 16);
        *(unsigned*)(smc + 34816 + (rl*136 + col)*2) = l0 | (l1 << 16);
        split_bf16(v10, h0, l0); split_bf16(v11, h1, l1);
        *(unsigned*)(smc + ((rl+8)*136 + col)*2)         = h0 | (h1 << 16);
        *(unsigned*)(smc + 34816 + ((rl+8)*136 + col)*2) = l0 | (l1 << 16);
    }
    __syncthreads();
    #pragma unroll
    for (int i = 0; i < 8; i++)
        #pragma unroll
        for (int j = 0; j < 4; j++) acc[i][j] = 0.f;
    hmma_gemm(sb, sb + 34816, sb + 69632, sb + 104448, m0, n0, lane, acc);
    #pragma unroll
    for (int s = 0; s < 8; s++) {
        int col = n0 + s*8 + (lane & 3)*2;
        acc[s][0] += bb[128+col]; acc[s][1] += bb[128+col+1];
        acc[s][2] += bb[128+col]; acc[s][3] += bb[128+col+1];
        int ra = row0 + rl, rb = ra + 8;
        if (ra < Nn) *(float2*)(g_feat + (size_t)ra*128 + col) = make_float2(acc[s][0], acc[s][1]);
        if (rb < Nn) *(float2*)(g_feat + (size_t)rb*128 + col) = make_float2(acc[s][2], acc[s][3]);
    }
    if (next < 0) return;

    __syncthreads();
    {
        const char* ah = (const char*)(g_Wbh + (size_t)(next*8 + 3)*17408);
        const char* al = (const char*)(g_Wbl + (size_t)(next*8 + 3)*17408);
        const char* bh = (const char*)(g_Wbh + (size_t)(next*8 + 4)*17408);
        const char* bl = (const char*)(g_Wbl + (size_t)(next*8 + 4)*17408);
        for (int i = tid; i < 2176; i += 512) {
            asm volatile("cp.async.cg.shared.global [%0], [%1], 16;"
                :: "r"(sb + 69632u + (unsigned)i*16u), "l"(ah + (size_t)i*16) : "memory");
            asm volatile("cp.async.cg.shared.global [%0], [%1], 16;"
                :: "r"(sb + 104448u + (unsigned)i*16u), "l"(al + (size_t)i*16) : "memory");
            asm volatile("cp.async.cg.shared.global [%0], [%1], 16;"
                :: "r"(sb + 139264u + (unsigned)i*16u), "l"(bh + (size_t)i*16) : "memory");
            asm volatile("cp.async.cg.shared.global [%0], [%1], 16;"
                :: "r"(sb + 174080u + (unsigned)i*16u), "l"(bl + (size_t)i*16) : "memory");
        }
        asm volatile("cp.async.commit_group;" ::: "memory");
    }
    #pragma unroll
    for (int s = 0; s < 8; s++) {
        int col = n0 + s*8 + (lane & 3)*2;
        unsigned h0, l0, h1, l1;
        split_bf16(acc[s][0], h0, l0); split_bf16(acc[s][1], h1, l1);
        *(unsigned*)(smc + (rl*136 + col)*2)         = h0 | (h1 << 16);
        *(unsigned*)(smc + 34816 + (rl*136 + col)*2) = l0 | (l1 << 16);
        split_bf16(acc[s][2], h0, l0); split_bf16(acc[s][3], h1, l1);
        *(unsigned*)(smc + ((rl+8)*136 + col)*2)         = h0 | (h1 << 16);
        *(unsigned*)(smc + 34816 + ((rl+8)*136 + col)*2) = l0 | (l1 << 16);
    }
    asm volatile("cp.async.wait_group 0;" ::: "memory");
    __syncthreads();

    #pragma unroll
    for (int i = 0; i < 8; i++)
        #pragma unroll
        for (int j = 0; j < 4; j++) acc[i][j] = 0.f;
    hmma_gemm(sb, sb + 34816, sb + 69632, sb + 104448, m0, n0, lane, acc);
    #pragma unroll
    for (int s = 0; s < 8; s++) {
        int col = n0 + s*8 + (lane & 3)*2;
        int ra = row0 + rl, rb = ra + 8;
        if (ra < Nn) *(float2*)(g_featA + (size_t)ra*128 + col) = make_float2(acc[s][0], acc[s][1]);
        if (rb < Nn) *(float2*)(g_featA + (size_t)rb*128 + col) = make_float2(acc[s][2], acc[s][3]);
    }
    #pragma unroll
    for (int i = 0; i < 8; i++)
        #pragma unroll
        for (int j = 0; j < 4; j++) acc[i][j] = 0.f;
    hmma_gemm(sb, sb + 34816, sb + 139264, sb + 174080, m0, n0, lane, acc);
    #pragma unroll
    for (int s = 0; s < 8; s++) {
        int col = n0 + s*8 + (lane & 3)*2;
        int ra = row0 + rl, rb = ra + 8;
        if (ra < Nn) *(float2*)(g_featB + (size_t)ra*128 + col) = make_float2(acc[s][0], acc[s][1]);
        if (rb < Nn) *(float2*)(g_featB + (size_t)rb*128 + col) = make_float2(acc[s][2], acc[s][3]);
    }
}

// ============ FUSED edge kernel: 32x32 tiles, fused p+s GEMM ============
// bytes: Ah 0 | Al 34816 | W1h 69632 | W1l 104448 | W2h 139264 | W2l 174080 |
// scal 208896 | bh 210944 | bhp 211456 | bhs 211968 | w2p 212480 | w2s 212992 |
// pd 214528 ([4][128][4] = 8192) | ridx 222720 | cidx 223232 | wtl 223744 -> 226304
#define FU_SMEM 226304
__global__ void __launch_bounds__(512, 1)
edge_fused_mma(const float* __restrict__ bm2l,
               const float* __restrict__ Wm1tail, const float* __restrict__ bm1l,
               const float* __restrict__ bp1l, const float* __restrict__ Wp2l,
               const float* __restrict__ bp2l,
               const float* __restrict__ bs1l, const float* __restrict__ Ws2l,
               const float* __restrict__ bs2l, int layer) {
    extern __shared__ char smc[];
    unsigned sb = smem_u32(smc);
    float* scal = (float*)(smc + 208896);
    float* bh   = (float*)(smc + 210944);
    float* bhp  = (float*)(smc + 211456);
    float* bhs  = (float*)(smc + 211968);
    float* w2p  = (float*)(smc + 212480);
    float* w2s  = (float*)(smc + 212992);
    float* pd   = (float*)(smc + 214528);   // [4][128][4]
    int* ridx   = (int*)(smc + 222720);
    int* cidx   = (int*)(smc + 223232);
    float* wtl  = (float*)(smc + 223744);
    int tid = threadIdx.x, w = tid >> 5, lane = tid & 31;

    const char* Wm2h = (const char*)(g_Wbh + (size_t)(layer*8 + 0)*17408);
    const char* Wm2l = (const char*)(g_Wbl + (size_t)(layer*8 + 0)*17408);
    const char* Wp1h = (const char*)(g_Wbh + (size_t)(layer*8 + 1)*17408);
    const char* Wp1l = (const char*)(g_Wbl + (size_t)(layer*8 + 1)*17408);
    const char* Ws1h = (const char*)(g_Wbh + (size_t)(layer*8 + 2)*17408);
    const char* Ws1l = (const char*)(g_Wbl + (size_t)(layer*8 + 2)*17408);

    // pin Ws1 in W2 for the whole layer
    {
        const uint4* mh = (const uint4*)Ws1h;
        const uint4* ml = (const uint4*)Ws1l;
        uint4* d2h = (uint4*)(smc + 139264);
        uint4* d2l = (uint4*)(smc + 174080);
        for (int i = tid; i < 2176; i += 512) { d2h[i] = mh[i]; d2l[i] = ml[i]; }
    }
    if (tid < 128) {
        bh[tid] = bm2l[tid]; bhp[tid] = bp1l[tid]; bhs[tid] = bs1l[tid];
        w2p[tid] = Wp2l[tid];
        w2s[tid*3+0] = Ws2l[tid*3+0]; w2s[tid*3+1] = Ws2l[tid*3+1]; w2s[tid*3+2] = Ws2l[tid*3+2];
    }
    for (int i = tid; i < 640; i += 512)
        wtl[i] = (i < 512) ? Wm1tail[i] : bm1l[i - 512];

    int m0 = (w & 3)*32, n0 = (w >> 2)*32;
    int ngrp = w >> 2;
    int rl = lane >> 2, cq = (lane & 3)*2;

    for (int t = blockIdx.x; t < NT; t += gridDim.x) {
        int e0 = t*128;
        __syncthreads();   // prev tile fully done; Ws1 fill visible (1st iter)
        // async-load Wm2 -> W1; hides under scal + h-build
        for (int i = tid; i < 2176; i += 512) {
            asm volatile("cp.async.cg.shared.global [%0], [%1], 16;"
                :: "r"(sb + 69632u + (unsigned)i*16u), "l"(Wm2h + (size_t)i*16) : "memory");
            asm volatile("cp.async.cg.shared.global [%0], [%1], 16;"
                :: "r"(sb + 104448u + (unsigned)i*16u), "l"(Wm2l + (size_t)i*16) : "memory");
        }
        asm volatile("cp.async.commit_group;" ::: "memory");
        if (tid < 128) {
            int r = g_er[e0 + tid], c = g_ec[e0 + tid];
            ridx[tid] = r; cidx[tid] = c;
            float dp0 = g_pos[r*3+0] - g_pos[c*3+0];
            float dp1 = g_pos[r*3+1] - g_pos[c*3+1];
            float dp2 = g_pos[r*3+2] - g_pos[c*3+2];
            float ip2 = 0.f;
            #pragma unroll
            for (int q = 4; q < 9; q++) ip2 += g_sh[r*9+q]*g_sh[c*9+q];
            scal[tid*4+0] = dp0*dp0 + dp1*dp1 + dp2*dp2;
            scal[tid*4+1] = g_sh[r*9+0]*g_sh[c*9+0];
            scal[tid*4+2] = g_sh[r*9+1]*g_sh[c*9+1] + g_sh[r*9+2]*g_sh[c*9+2] + g_sh[r*9+3]*g_sh[c*9+3];
            scal[tid*4+3] = ip2;
        }
        __syncthreads();
        #pragma unroll
        for (int q = 0; q < 8; q++) {
            int idx = tid + q*512;
            int e = idx >> 5, c4 = (idx & 31)*4;
            int r = ridx[e], c = cidx[e];
            float4 fa = *(const float4*)(g_featA + (size_t)r*128 + c4);
            float4 fb = *(const float4*)(g_featB + (size_t)c*128 + c4);
            float d2 = scal[e*4+0], i0 = scal[e*4+1], i1 = scal[e*4+2], i2 = scal[e*4+3];
            float hv[4];
            hv[0] = silu_f(fa.x + fb.x + d2*wtl[c4+0] + i0*wtl[128+c4+0] + i1*wtl[256+c4+0] + i2*wtl[384+c4+0] + wtl[512+c4+0]);
            hv[1] = silu_f(fa.y + fb.y + d2*wtl[c4+1] + i0*wtl[128+c4+1] + i1*wtl[256+c4+1] + i2*wtl[384+c4+1] + wtl[512+c4+1]);
            hv[2] = silu_f(fa.z + fb.z + d2*wtl[c4+2] + i0*wtl[128+c4+2] + i1*wtl[256+c4+2] + i2*wtl[384+c4+2] + wtl[512+c4+2]);
            hv[3] = silu_f(fa.w + fb.w + d2*wtl[c4+3] + i0*wtl[128+c4+3] + i1*wtl[256+c4+3] + i2*wtl[384+c4+3] + wtl[512+c4+3]);
            unsigned h[4], l[4];
            #pragma unroll
            for (int j = 0; j < 4; j++) split_bf16(hv[j], h[j], l[j]);
            unsigned off = (unsigned)(e*136 + c4)*2u;
            *(uint2*)(smc + off)         = make_uint2(h[0]|(h[1]<<16), h[2]|(h[3]<<16));
            *(uint2*)(smc + 34816 + off) = make_uint2(l[0]|(l[1]<<16), l[2]|(l[3]<<16));
        }
        asm volatile("cp.async.wait_group 0;" ::: "memory");   // Wm2 in W1
        __syncthreads();

        // GEMM1: m = h @ Wm2 (32x32 tiles)
        float acc[2][4][4];
        #pragma unroll
        for (int i = 0; i < 2; i++)
            #pragma unroll
            for (int j = 0; j < 4; j++)
                #pragma unroll
                for (int k = 0; k < 4; k++) acc[i][j][k] = 0.f;
        hmma_g32(sb, sb + 34816, sb + 69632, sb + 104448, m0, n0, lane, acc);
        __syncthreads();   // A + W1 reads done

        // async-load Wp1 -> W1; hides under m epilogue
        for (int i = tid; i < 2176; i += 512) {
            asm volatile("cp.async.cg.shared.global [%0], [%1], 16;"
                :: "r"(sb + 69632u + (unsigned)i*16u), "l"(Wp1h + (size_t)i*16) : "memory");
            asm volatile("cp.async.cg.shared.global [%0], [%1], 16;"
                :: "r"(sb + 104448u + (unsigned)i*16u), "l"(Wp1l + (size_t)i*16) : "memory");
        }
        asm volatile("cp.async.commit_group;" ::: "memory");
        // m epilogue: split into A
        #pragma unroll
        for (int mf = 0; mf < 2; mf++) {
            int r0 = m0 + mf*16 + rl, r1 = r0 + 8;
            #pragma unroll
            for (int nm = 0; nm < 4; nm++) {
                int col = n0 + nm*8 + cq;
                float v00 = silu_f(acc[mf][nm][0] + bh[col]);
                float v01 = silu_f(acc[mf][nm][1] + bh[col+1]);
                float v10 = silu_f(acc[mf][nm][2] + bh[col]);
                float v11 = silu_f(acc[mf][nm][3] + bh[col+1]);
                unsigned h0, l0, h1, l1;
                split_bf16(v00, h0, l0); split_bf16(v01, h1, l1);
                *(unsigned*)(smc + (r0*136 + col)*2)         = h0 | (h1 << 16);
                *(unsigned*)(smc + 34816 + (r0*136 + col)*2) = l0 | (l1 << 16);
                split_bf16(v10, h0, l0); split_bf16(v11, h1, l1);
                *(unsigned*)(smc + (r1*136 + col)*2)         = h0 | (h1 << 16);
                *(unsigned*)(smc + 34816 + (r1*136 + col)*2) = l0 | (l1 << 16);
            }
        }
        asm volatile("cp.async.wait_group 0;" ::: "memory");   // Wp1 in W1
        __syncthreads();

        // fused GEMM2+3: p = m @ Wp1, s = m @ Ws1
        float accp[2][4][4], accs[2][4][4];
        #pragma unroll
        for (int i = 0; i < 2; i++)
            #pragma unroll
            for (int j = 0; j < 4; j++)
                #pragma unroll
                for (int k = 0; k < 4; k++) { accp[i][j][k] = 0.f; accs[i][j][k] = 0.f; }
        hmma_g32x2(sb, sb + 34816, sb + 69632, sb + 104448,
                   sb + 139264, sb + 174080, m0, n0, lane, accp, accs);
        // epilogue: per-row dots + quad reduce -> pd[ngrp]
        {
            float pr[2][2], s0v[2][2], s1v[2][2], s2v[2][2];
            #pragma unroll
            for (int mf = 0; mf < 2; mf++) {
                float p0 = 0.f, p1 = 0.f;
                float a0 = 0.f, a1 = 0.f, b0 = 0.f, b1 = 0.f, c0 = 0.f, c1 = 0.f;
                #pragma unroll
                for (int nm = 0; nm < 4; nm++) {
                    int col = n0 + nm*8 + cq;
                    float h00 = silu_f(accp[mf][nm][0] + bhp[col]);
                    float h01 = silu_f(accp[mf][nm][1] + bhp[col+1]);
                    float h10 = silu_f(accp[mf][nm][2] + bhp[col]);
                    float h11 = silu_f(accp[mf][nm][3] + bhp[col+1]);
                    p0 = fmaf(h00, w2p[col], fmaf(h01, w2p[col+1], p0));
                    p1 = fmaf(h10, w2p[col], fmaf(h11, w2p[col+1], p1));
                    float g00 = silu_f(accs[mf][nm][0] + bhs[col]);
                    float g01 = silu_f(accs[mf][nm][1] + bhs[col+1]);
                    float g10 = silu_f(accs[mf][nm][2] + bhs[col]);
                    float g11 = silu_f(accs[mf][nm][3] + bhs[col+1]);
                    a0 = fmaf(g00, w2s[col*3+0], fmaf(g01, w2s[(col+1)*3+0], a0));
                    b0 = fmaf(g00, w2s[col*3+1], fmaf(g01, w2s[(col+1)*3+1], b0));
                    c0 = fmaf(g00, w2s[col*3+2], fmaf(g01, w2s[(col+1)*3+2], c0));
                    a1 = fmaf(g10, w2s[col*3+0], fmaf(g11, w2s[(col+1)*3+0], a1));
                    b1 = fmaf(g10, w2s[col*3+1], fmaf(g11, w2s[(col+1)*3+1], b1));
                    c1 = fmaf(g10, w2s[col*3+2], fmaf(g11, w2s[(col+1)*3+2], c1));
                }
                pr[mf][0] = p0; pr[mf][1] = p1;
                s0v[mf][0] = a0; s0v[mf][1] = a1;
                s1v[mf][0] = b0; s1v[mf][1] = b1;
                s2v[mf][0] = c0; s2v[mf][1] = c1;
            }
            #pragma unroll
            for (int off = 1; off <= 2; off <<= 1) {
                #pragma unroll
                for (int mf = 0; mf < 2; mf++)
                    #pragma unroll
                    for (int hh = 0; hh < 2; hh++) {
                        pr[mf][hh]  += __shfl_xor_sync(0xffffffffu, pr[mf][hh],  off);
                        s0v[mf][hh] += __shfl_xor_sync(0xffffffffu, s0v[mf][hh], off);
                        s1v[mf][hh] += __shfl_xor_sync(0xffffffffu, s1v[mf][hh], off);
                        s2v[mf][hh] += __shfl_xor_sync(0xffffffffu, s2v[mf][hh], off);
                    }
            }
            if ((lane & 3) == 0) {
                #pragma unroll
                for (int mf = 0; mf < 2; mf++)
                    #pragma unroll
                    for (int hh = 0; hh < 2; hh++) {
                        int r = m0 + mf*16 + rl + hh*8;
                        float* p = pd + ngrp*512 + r*4;
                        p[0] = pr[mf][hh]; p[1] = s0v[mf][hh];
                        p[2] = s1v[mf][hh]; p[3] = s2v[mf][hh];
                    }
            }
        }
        __syncthreads();
        // scatters (sum 4 n-groups) + msum walk from split-bf16 A
        if (tid < 128) {
            int r = ridx[tid], c = cidx[tid];
            float psc = bp2l[0], s0 = bs2l[0], s1 = bs2l[1], s2 = bs2l[2];
            #pragma unroll
            for (int g = 0; g < 4; g++) {
                const float* p = pd + g*512 + tid*4;
                psc += p[0]; s0 += p[1]; s1 += p[2]; s2 += p[3];
            }
            float dp0 = g_pos[r*3+0] - g_pos[c*3+0];
            float dp1 = g_pos[r*3+1] - g_pos[c*3+1];
            float dp2 = g_pos[r*3+2] - g_pos[c*3+2];
            atomicAdd(&g_psum[r*3+0], dp0*psc);
            atomicAdd(&g_psum[r*3+1], dp1*psc);
            atomicAdd(&g_psum[r*3+2], dp2*psc);
            #pragma unroll
            for (int q = 0; q < 9; q++) {
                float diff = g_sh[r*9+q] - g_sh[c*9+q];
                atomicAdd(&g_ssum[r*9+q], diff * ((q == 0) ? s0 : (q < 4) ? s1 : s2));
            }
        }
        {
            int c = tid & 127, seg = tid >> 7;
            int eb = seg*32;
            float agg = 0.f;
            int ar = ridx[eb];
            for (int e = eb; e < eb + 32; e++) {
                ush hi = *(const ush*)(smc + (e*136 + c)*2);
                ush lo = *(const ush*)(smc + 34816 + (e*136 + c)*2);
                float v = __bfloat162float(__ushort_as_bfloat16(hi))
                        + __bfloat162float(__ushort_as_bfloat16(lo));
                int r = ridx[e];
                if (r != ar) { atomicAdd(&g_msum[(size_t)ar*128 + c], agg); agg = v; ar = r; }
                else agg += v;
            }
            atomicAdd(&g_msum[(size_t)ar*128 + c], agg);
        }
    }
}

// posh also zeroes psum/ssum for the next layer
__global__ void posh_kernel() {
    int i = blockIdx.x*256 + threadIdx.x;
    if (i >= Nn) return;
    float inv = 1.0f / fmaxf(g_deg[i], 1.0f);
    #pragma unroll
    for (int q = 0; q < 3; q++) {
        g_pos[i*3+q] += g_psum[i*3+q]*inv;
        g_psum[i*3+q] = 0.0f;
    }
    #pragma unroll
    for (int q = 0; q < 9; q++) {
        g_sh[i*9+q] += g_ssum[i*9+q]*inv;
        g_ssum[i*9+q] = 0.0f;
    }
}
__global__ void pool_kernel(const int* __restrict__ batch) {
    int idx = blockIdx.x*256 + threadIdx.x;
    if (idx >= Nn*140) return;
    int i = idx / 140, c = idx % 140;
    float v;
    if (c < 128)      v = g_feat[(size_t)i*128 + c];
    else if (c < 131) v = g_pos[i*3 + (c - 128)];
    else              v = g_sh[i*9 + (c - 131)];
    atomicAdd(&g_pool[batch[i]*140 + c], v);
}
__global__ void pred_kernel(const float* __restrict__ Wpred, const float* __restrict__ bpred,
                            float* __restrict__ out) {
    int g = blockIdx.x, lane = threadIdx.x;
    float s = 0.f;
    for (int c = lane; c < 140; c += 32)
        s = fmaf(g_pool[g*140 + c], Wpred[c], s);
    #pragma unroll
    for (int off = 16; off > 0; off >>= 1)
        s += __shfl_xor_sync(0xffffffffu, s, off);
    if (lane == 0) out[g] = s + bpred[0];
}

extern "C" void kernel_launch(void* const* d_in, const int* in_sizes, int n_in,
                              void* d_out, int out_size) {
    const int*   atoms = (const int*)d_in[0];
    const int*   ei    = (const int*)d_in[1];
    const int*   batch = (const int*)d_in[2];
    const float* pos   = (const float*)d_in[3];
    const float* emb   = (const float*)d_in[4];
    const float* Wsi1  = (const float*)d_in[5];  const float* bsi1  = (const float*)d_in[6];
    const float* Wsi2  = (const float*)d_in[7];  const float* bsi2  = (const float*)d_in[8];
    const float* WsiC1 = (const float*)d_in[9];  const float* bsiC1 = (const float*)d_in[10];
    const float* WsiC2 = (const float*)d_in[11]; const float* bsiC2 = (const float*)d_in[12];
    const float* Wm1   = (const float*)d_in[13]; const float* bm1   = (const float*)d_in[14];
    const float* Wm2   = (const float*)d_in[15]; const float* bm2   = (const float*)d_in[16];
    const float* Wp1   = (const float*)d_in[17]; const float* bp1   = (const float*)d_in[18];
    const float* Wp2   = (const float*)d_in[19]; const float* bp2   = (const float*)d_in[20];
    const float* Wn1   = (const float*)d_in[21]; const float* bn1   = (const float*)d_in[22];
    const float* Wn2   = (const float*)d_in[23]; const float* bn2   = (const float*)d_in[24];
    const float* Ws1   = (const float*)d_in[25]; const float* bs1   = (const float*)d_in[26];
    const float* Ws2   = (const float*)d_in[27]; const float* bs2   = (const float*)d_in[28];
    const float* Wpred = (const float*)d_in[29]; const float* bpred = (const float*)d_in[30];
    float* out = (float*)d_out;

    cudaFuncSetAttribute(featab_mma, cudaFuncAttributeMaxDynamicSharedMemorySize, FABM_SMEM);
    cudaFuncSetAttribute(nodeup_mma, cudaFuncAttributeMaxDynamicSharedMemorySize, NUM_SMEM);
    cudaFuncSetAttribute(edge_fused_mma, cudaFuncAttributeMaxDynamicSharedMemorySize, FU_SMEM);

    void *p_msum, *p_psum, *p_ssum, *p_deg, *p_com, *p_cnt, *p_pool, *p_pos, *p_cur;
    cudaGetSymbolAddress(&p_msum, g_msum);
    cudaGetSymbolAddress(&p_psum, g_psum);
    cudaGetSymbolAddress(&p_ssum, g_ssum);
    cudaGetSymbolAddress(&p_deg,  g_deg);
    cudaGetSymbolAddress(&p_com,  g_com);
    cudaGetSymbolAddress(&p_cnt,  g_cnt);
    cudaGetSymbolAddress(&p_pool, g_pool);
    cudaGetSymbolAddress(&p_pos,  g_pos);
    cudaGetSymbolAddress(&p_cur,  g_cursor);

    cudaMemsetAsync(p_deg,  0, Nn*4, 0);
    cudaMemsetAsync(p_com,  0, Gg*3*4, 0);
    cudaMemsetAsync(p_cnt,  0, Gg*4, 0);
    cudaMemsetAsync(p_ssum, 0, Nn*9*4, 0);
    cudaMemsetAsync(p_psum, 0, Nn*3*4, 0);
    cudaMemsetAsync(p_msum, 0, (size_t)Nn*128*4, 0);
    cudaMemsetAsync(p_pool, 0, Gg*140*4, 0);
    cudaMemsetAsync(p_cur,  0, Nn*4, 0);
    cudaMemcpyAsync(p_pos, pos, Nn*3*4, cudaMemcpyDeviceToDevice, 0);

    wprep_kernel<<<40, 256>>>(Wm2, Wp1, Ws1, Wm1, Wn1, Wn2);
    node_init_kernel<<<(Nn*128)/256, 256>>>(atoms, emb);
    com_kernel<<<(Nn + 255)/256, 256>>>(batch);
    deg_kernel<<<(Ee + 255)/256, 256>>>(ei);
    scan_kernel<<<1, 256>>>();
    sortscatter_kernel<<<(Ee + 255)/256, 256>>>(ei);
    vocab_kernel<<<10, 128>>>(emb, Wsi1, WsiC1, bsiC1, WsiC2, bsiC2);
    edge_init_kernel<<<Ee/8, 256>>>(atoms, Wsi1, bsi1, Wsi2, bsi2);
    sh_init_kernel<<<(Nn + 255)/256, 256>>>(atoms, batch);

    int gridNM = (Nn + 127)/128;   // 79

    featab_mma<<<gridNM, 512, FABM_SMEM>>>(0);

    for (int l = 0; l < Ll; l++) {
        edge_fused_mma<<<148, 512, FU_SMEM>>>(
            bm2 + l*128,
            Wm1 + ((size_t)l*260 + 256)*128, bm1 + l*128,
            bp1 + l*128, Wp2 + l*128, bp2 + l,
            bs1 + l*128, Ws2 + l*384, bs2 + l*3, l);

        posh_kernel<<<(Nn + 255)/256, 256>>>();

        nodeup_mma<<<gridNM, 512, NUM_SMEM>>>(bn1 + l*128, bn2 + l*128, l,
                                              (l + 1 < Ll) ? (l + 1) : -1);
    }

    pool_kernel<<<(Nn*140 + 255)/256, 256>>>(batch);
    pred_kernel<<<Gg, 32>>>(Wpred, bpred, out);
}

// round 16
// speedup vs baseline: 1.1440x; 1.1440x over previous
#include <cuda_runtime.h>
#include <cuda_bf16.h>
#include <cstdint>
#include <math.h>

#define Nn 10000
#define Ee 160000
#define Gg 100
#define Ll 5
#define NT 2500   // 64-edge tiles (edge kernel)

typedef unsigned long long u64;
typedef unsigned short ush;

__device__ float g_feat [Nn*128];
__device__ float g_featA[Nn*128];
__device__ float g_featB[Nn*128];
__device__ float g_sh   [Nn*9];
__device__ float g_pos  [Nn*3];
__device__ float g_msum [Nn*128];
__device__ float g_psum [Nn*3];
__device__ float g_ssum [Nn*9];
__device__ float g_deg  [Nn];
__device__ float g_com  [Gg*3];
__device__ float g_cnt  [Gg];
__device__ float g_P1   [10*128];
__device__ float g_P2   [10*128];
__device__ float g_cmsg [10];
__device__ float g_pool [Gg*140];
__device__ int   g_off  [Nn];
__device__ int   g_cursor[Nn];
__device__ int   g_er   [Ee];
__device__ int   g_ec   [Ee];
__device__ ush   g_Wbh [40*17408];          // [l*8+slot][n*136+k] hi
__device__ ush   g_Wbl [40*17408];          // lo

__device__ __forceinline__ float silu_f(float x) { return x / (1.0f + __expf(-x)); }

__device__ __forceinline__ void sph2(float vx, float vy, float vz, float* o) {
    const float S3 = 1.7320508075688772f, HS3 = 0.8660254037844386f;
    float r = sqrtf(vx*vx + vy*vy + vz*vz);
    float inv = 1.0f / fmaxf(r, 1e-12f);
    float x = vx*inv, y = vy*inv, z = vz*inv;
    o[0] = S3*x*z; o[1] = S3*x*y; o[2] = y*y - 0.5f*(x*x + z*z);
    o[3] = S3*y*z; o[4] = HS3*(z*z - x*x);
}

// ---- HMMA helpers ----
__device__ __forceinline__ unsigned smem_u32(const void* p) {
    unsigned a; asm("{ .reg .u64 t; cvta.to.shared.u64 t, %1; cvt.u32.u64 %0, t; }" : "=r"(a) : "l"(p));
    return a;
}
__device__ __forceinline__ void ldsm4(unsigned addr, unsigned* r) {
    asm volatile("ldmatrix.sync.aligned.m8n8.x4.shared.b16 {%0,%1,%2,%3}, [%4];"
        : "=r"(r[0]), "=r"(r[1]), "=r"(r[2]), "=r"(r[3]) : "r"(addr));
}
__device__ __forceinline__ void mma_bf16(float* d, const unsigned* a, unsigned b0, unsigned b1) {
    asm volatile("mma.sync.aligned.m16n8k16.row.col.f32.bf16.bf16.f32 "
        "{%0,%1,%2,%3},{%4,%5,%6,%7},{%8,%9},{%0,%1,%2,%3};"
        : "+f"(d[0]), "+f"(d[1]), "+f"(d[2]), "+f"(d[3])
        : "r"(a[0]), "r"(a[1]), "r"(a[2]), "r"(a[3]), "r"(b0), "r"(b1));
}
__device__ __forceinline__ void split_bf16(float v, unsigned& h, unsigned& l) {
    __nv_bfloat16 hb = __float2bfloat16(v);
    h = (unsigned)__bfloat16_as_ushort(hb);
    l = (unsigned)__bfloat16_as_ushort(__float2bfloat16(v - __bfloat162float(hb)));
}

// split-bf16 GEMM core: rows m0..+15 x cols n0..+63, K=128; A/B ush stride 136 (272 B)
__device__ __forceinline__ void hmma_gemm(unsigned aH, unsigned aL, unsigned bH, unsigned bL,
                                          int m0, int n0, int lane, float acc[8][4]) {
    unsigned aoff = (unsigned)((m0 + (lane & 15))*272 + (lane >> 4)*16);
    unsigned boff = (unsigned)((n0 + (lane & 15))*272 + (lane >> 4)*16);
    #pragma unroll
    for (int kk = 0; kk < 8; kk++) {
        unsigned kb = kk*32;
        unsigned Ah[4], Al[4];
        ldsm4(aH + aoff + kb, Ah);
        ldsm4(aL + aoff + kb, Al);
        #pragma unroll
        for (int t = 0; t < 4; t++) {
            unsigned bo = boff + t*16*272 + kb;
            unsigned Bh[4], Bl[4];
            ldsm4(bH + bo, Bh);
            ldsm4(bL + bo, Bl);
            mma_bf16(acc[2*t],   Ah, Bh[0], Bh[2]);
            mma_bf16(acc[2*t],   Ah, Bl[0], Bl[2]);
            mma_bf16(acc[2*t],   Al, Bh[0], Bh[2]);
            mma_bf16(acc[2*t+1], Ah, Bh[1], Bh[3]);
            mma_bf16(acc[2*t+1], Ah, Bl[1], Bl[3]);
            mma_bf16(acc[2*t+1], Al, Bh[1], Bh[3]);
        }
    }
}

// weights -> split-bf16 [n][k] stride-136 tiles
// slot: 0 Wm2, 1 Wp1, 2 Ws1, 3 Wa, 4 Wb, 5 W5, 6 W6, 7 W7
__global__ void wprep_kernel(const float* __restrict__ Wm2, const float* __restrict__ Wp1,
                             const float* __restrict__ Ws1, const float* __restrict__ Wm1,
                             const float* __restrict__ Wn1, const float* __restrict__ Wn2) {
    int bid = blockIdx.x, l = bid >> 3, slot = bid & 7;
    const float* src;
    switch (slot) {
        case 0: src = Wm2 + (size_t)l*16384;              break;
        case 1: src = Wp1 + (size_t)l*16384;              break;
        case 2: src = Ws1 + (size_t)l*16384;              break;
        case 3: src = Wm1 + (size_t)l*260*128;            break;
        case 4: src = Wm1 + ((size_t)l*260 + 128)*128;    break;
        case 5: src = Wn1 + (size_t)l*256*128;            break;
        case 6: src = Wn1 + ((size_t)l*256 + 128)*128;    break;
        default:src = Wn2 + (size_t)l*16384;              break;
    }
    ush* dh = g_Wbh + (size_t)bid*17408;
    ush* dl = g_Wbl + (size_t)bid*17408;
    for (int o = threadIdx.x; o < 16384; o += 256) {
        int k = o >> 7, n = o & 127;
        unsigned h, lo;
        split_bf16(src[k*128 + n], h, lo);
        dh[n*136 + k] = (ush)h;
        dl[n*136 + k] = (ush)lo;
    }
}

// ---- init kernels ----
__global__ void node_init_kernel(const int* __restrict__ atoms, const float* __restrict__ emb) {
    int idx = blockIdx.x*256 + threadIdx.x;
    g_feat[idx] = emb[atoms[idx >> 7]*128 + (idx & 127)];
}
__global__ void com_kernel(const int* __restrict__ batch) {
    int i = blockIdx.x*256 + threadIdx.x;
    if (i >= Nn) return;
    int b = batch[i];
    atomicAdd(&g_com[b*3+0], g_pos[i*3+0]);
    atomicAdd(&g_com[b*3+1], g_pos[i*3+1]);
    atomicAdd(&g_com[b*3+2], g_pos[i*3+2]);
    atomicAdd(&g_cnt[b], 1.0f);
}
__global__ void deg_kernel(const int* __restrict__ ei) {
    int e = blockIdx.x*256 + threadIdx.x;
    if (e < Ee) atomicAdd(&g_deg[ei[e]], 1.0f);
}
__global__ void scan_kernel() {
    __shared__ int part[256];
    int tid = threadIdx.x;
    int lo = tid*40, hi = (lo + 40 < Nn) ? lo + 40 : Nn;
    int s = 0;
    for (int i = lo; i < hi; i++) s += (int)g_deg[i];
    part[tid] = s;
    __syncthreads();
    for (int off = 1; off < 256; off <<= 1) {
        int v = part[tid] + ((tid >= off) ? part[tid - off] : 0);
        __syncthreads(); part[tid] = v; __syncthreads();
    }
    int base = (tid > 0) ? part[tid - 1] : 0;
    for (int i = lo; i < hi; i++) { g_off[i] = base; base += (int)g_deg[i]; }
}
__global__ void sortscatter_kernel(const int* __restrict__ ei) {
    int e = blockIdx.x*256 + threadIdx.x;
    if (e >= Ee) return;
    int r = ei[e], c = ei[Ee + e];
    int p = g_off[r] + atomicAdd(&g_cursor[r], 1);
    g_er[p] = r; g_ec[p] = c;
}
__global__ void vocab_kernel(const float* __restrict__ emb, const float* __restrict__ Wsi1,
                             const float* __restrict__ WsiC1, const float* __restrict__ bsiC1,
                             const float* __restrict__ WsiC2, const float* __restrict__ bsiC2) {
    __shared__ float es[128], redv[128];
    int v = blockIdx.x, j = threadIdx.x;
    es[j] = emb[v*128 + j];
    __syncthreads();
    float p1 = 0.f, p2 = 0.f, hc = 0.f;
    for (int k = 0; k < 128; k++) {
        float e = es[k];
        p1 = fmaf(e, Wsi1[(1 + k)*128 + j], p1);
        p2 = fmaf(e, Wsi1[(129 + k)*128 + j], p2);
        hc = fmaf(e, WsiC1[k*128 + j], hc);
    }
    g_P1[v*128 + j] = p1; g_P2[v*128 + j] = p2;
    redv[j] = silu_f(hc + bsiC1[j]) * WsiC2[j*3 + 2];
    __syncthreads();
    for (int s = 64; s > 0; s >>= 1) {
        if (j < s) redv[j] += redv[j + s];
        __syncthreads();
    }
    if (j == 0) g_cmsg[v] = redv[0] + bsiC2[2];
}
__global__ void edge_init_kernel(const int* __restrict__ atoms,
                                 const float* __restrict__ Wsi1, const float* __restrict__ bsi1,
                                 const float* __restrict__ Wsi2, const float* __restrict__ bsi2) {
    int e = blockIdx.x*8 + (threadIdx.x >> 5);
    int lane = threadIdx.x & 31;
    int r = g_er[e], c = g_ec[e];
    float dp0 = g_pos[r*3+0] - g_pos[c*3+0];
    float dp1 = g_pos[r*3+1] - g_pos[c*3+1];
    float dp2 = g_pos[r*3+2] - g_pos[c*3+2];
    float dist = sqrtf(dp0*dp0 + dp1*dp1 + dp2*dp2);
    int ar = atoms[r], ac = atoms[c];
    float partial = 0.f;
    #pragma unroll
    for (int q = 0; q < 4; q++) {
        int d = lane + q*32;
        partial = fmaf(silu_f(dist*Wsi1[d] + g_P1[ar*128 + d] + g_P2[ac*128 + d] + bsi1[d]),
                       Wsi2[d*3 + 2], partial);
    }
    #pragma unroll
    for (int off = 16; off > 0; off >>= 1)
        partial += __shfl_xor_sync(0xffffffffu, partial, off);
    if (lane == 0) {
        float msg2 = partial + bsi2[2];
        float y2[5];
        sph2(dp0, dp1, dp2, y2);
        #pragma unroll
        for (int q = 0; q < 5; q++)
            atomicAdd(&g_ssum[r*9 + 4 + q], y2[q]*msg2);
    }
}
__global__ void sh_init_kernel(const int* __restrict__ atoms, const int* __restrict__ batch) {
    int i = blockIdx.x*256 + threadIdx.x;
    if (i >= Nn) return;
    float dg = fmaxf(g_deg[i], 1.0f);
    int b = batch[i];
    float cn = fmaxf(g_cnt[b], 1.0f);
    float y2[5];
    sph2(g_pos[i*3+0] - g_com[b*3+0]/cn, g_pos[i*3+1] - g_com[b*3+1]/cn,
         g_pos[i*3+2] - g_com[b*3+2]/cn, y2);
    float cm = g_cmsg[atoms[i]];
    #pragma unroll
    for (int q = 0; q < 4; q++) g_sh[i*9 + q] = 0.0f;
    #pragma unroll
    for (int q = 0; q < 5; q++)
        g_sh[i*9 + 4 + q] = g_ssum[i*9 + 4 + q]/dg + cm*y2[q];
    #pragma unroll
    for (int q = 0; q < 9; q++) g_ssum[i*9 + q] = 0.0f;
}

// ============ featAB via HMMA (layer 0 only, proven) ============
#define FABM_SMEM 208896
__global__ void __launch_bounds__(512, 1)
featab_mma(int layer) {
    extern __shared__ char smc[];
    unsigned sb = smem_u32(smc);
    int tid = threadIdx.x, w = tid >> 5, lane = tid & 31;
    int row0 = blockIdx.x * 128;

    {
        const uint4* ah = (const uint4*)(g_Wbh + (size_t)(layer*8 + 3)*17408);
        const uint4* al = (const uint4*)(g_Wbl + (size_t)(layer*8 + 3)*17408);
        const uint4* bh = (const uint4*)(g_Wbh + (size_t)(layer*8 + 4)*17408);
        const uint4* bl = (const uint4*)(g_Wbl + (size_t)(layer*8 + 4)*17408);
        uint4* dah = (uint4*)(smc + 69632);
        uint4* dal = (uint4*)(smc + 104448);
        uint4* dbh = (uint4*)(smc + 139264);
        uint4* dbl = (uint4*)(smc + 174080);
        for (int i = tid; i < 2176; i += 512) {
            dah[i] = ah[i]; dal[i] = al[i]; dbh[i] = bh[i]; dbl[i] = bl[i];
        }
    }
    #pragma unroll
    for (int q = 0; q < 8; q++) {
        int idx = tid + q*512;
        int r = idx >> 5, c4 = (idx & 31)*4;
        float4 v = make_float4(0.f,0.f,0.f,0.f);
        if (row0 + r < Nn) v = *(const float4*)(g_feat + (size_t)(row0 + r)*128 + c4);
        unsigned h[4], l[4];
        split_bf16(v.x, h[0], l[0]); split_bf16(v.y, h[1], l[1]);
        split_bf16(v.z, h[2], l[2]); split_bf16(v.w, h[3], l[3]);
        unsigned off = (unsigned)(r*136 + c4)*2u;
        *(uint2*)(smc + off)         = make_uint2(h[0]|(h[1]<<16), h[2]|(h[3]<<16));
        *(uint2*)(smc + 34816 + off) = make_uint2(l[0]|(l[1]<<16), l[2]|(l[3]<<16));
    }
    __syncthreads();

    int m0 = (w & 7)*16, n0 = (w >> 3)*64;
    int rl = m0 + (lane >> 2);
    float acc[8][4];
    #pragma unroll
    for (int i = 0; i < 8; i++)
        #pragma unroll
        for (int j = 0; j < 4; j++) acc[i][j] = 0.f;
    hmma_gemm(sb, sb + 34816, sb + 69632, sb + 104448, m0, n0, lane, acc);
    #pragma unroll
    for (int s = 0; s < 8; s++) {
        int col = n0 + s*8 + (lane & 3)*2;
        int ra = row0 + rl, rb = ra + 8;
        if (ra < Nn) *(float2*)(g_featA + (size_t)ra*128 + col) = make_float2(acc[s][0], acc[s][1]);
        if (rb < Nn) *(float2*)(g_featA + (size_t)rb*128 + col) = make_float2(acc[s][2], acc[s][3]);
    }
    #pragma unroll
    for (int i = 0; i < 8; i++)
        #pragma unroll
        for (int j = 0; j < 4; j++) acc[i][j] = 0.f;
    hmma_gemm(sb, sb + 34816, sb + 139264, sb + 174080, m0, n0, lane, acc);
    #pragma unroll
    for (int s = 0; s < 8; s++) {
        int col = n0 + s*8 + (lane & 3)*2;
        int ra = row0 + rl, rb = ra + 8;
        if (ra < Nn) *(float2*)(g_featB + (size_t)ra*128 + col) = make_float2(acc[s][0], acc[s][1]);
        if (rb < Nn) *(float2*)(g_featB + (size_t)rb*128 + col) = make_float2(acc[s][2], acc[s][3]);
    }
}

// ============ node update via HMMA + fused featAB for next layer (proven) ============
#define NUM_SMEM 209920
__global__ void __launch_bounds__(512, 1)
nodeup_mma(const float* __restrict__ b1, const float* __restrict__ b2, int layer, int next) {
    extern __shared__ char smc[];
    unsigned sb = smem_u32(smc);
    float* bb = (float*)(smc + 208896);
    int tid = threadIdx.x, w = tid >> 5, lane = tid & 31;
    int row0 = blockIdx.x * 128;

    {
        const uint4* ah = (const uint4*)(g_Wbh + (size_t)(layer*8 + 5)*17408);
        const uint4* al = (const uint4*)(g_Wbl + (size_t)(layer*8 + 5)*17408);
        const uint4* bh = (const uint4*)(g_Wbh + (size_t)(layer*8 + 6)*17408);
        const uint4* bl = (const uint4*)(g_Wbl + (size_t)(layer*8 + 6)*17408);
        uint4* d1h = (uint4*)(smc + 69632);
        uint4* d1l = (uint4*)(smc + 104448);
        uint4* d2h = (uint4*)(smc + 139264);
        uint4* d2l = (uint4*)(smc + 174080);
        for (int i = tid; i < 2176; i += 512) {
            d1h[i] = ah[i]; d1l[i] = al[i]; d2h[i] = bh[i]; d2l[i] = bl[i];
        }
    }
    if (tid < 128) { bb[tid] = b1[tid]; bb[128 + tid] = b2[tid]; }
    #pragma unroll
    for (int q = 0; q < 8; q++) {
        int idx = tid + q*512;
        int r = idx >> 5, c4 = (idx & 31)*4;
        float4 v = make_float4(0.f,0.f,0.f,0.f);
        if (row0 + r < Nn) v = *(const float4*)(g_feat + (size_t)(row0 + r)*128 + c4);
        unsigned h[4], l[4];
        split_bf16(v.x, h[0], l[0]); split_bf16(v.y, h[1], l[1]);
        split_bf16(v.z, h[2], l[2]); split_bf16(v.w, h[3], l[3]);
        unsigned off = (unsigned)(r*136 + c4)*2u;
        *(uint2*)(smc + off)         = make_uint2(h[0]|(h[1]<<16), h[2]|(h[3]<<16));
        *(uint2*)(smc + 34816 + off) = make_uint2(l[0]|(l[1]<<16), l[2]|(l[3]<<16));
    }
    __syncthreads();

    int m0 = (w & 7)*16, n0 = (w >> 3)*64;
    int rl = m0 + (lane >> 2);
    float acc[8][4];
    #pragma unroll
    for (int i = 0; i < 8; i++)
        #pragma unroll
        for (int j = 0; j < 4; j++) acc[i][j] = 0.f;
    hmma_gemm(sb, sb + 34816, sb + 69632, sb + 104448, m0, n0, lane, acc);
    __syncthreads();

    {
        const uint4* ah = (const uint4*)(g_Wbh + (size_t)(layer*8 + 7)*17408);
        const uint4* al = (const uint4*)(g_Wbl + (size_t)(layer*8 + 7)*17408);
        uint4* d1h = (uint4*)(smc + 69632);
        uint4* d1l = (uint4*)(smc + 104448);
        for (int i = tid; i < 2176; i += 512) { d1h[i] = ah[i]; d1l[i] = al[i]; }
    }
    #pragma unroll
    for (int q = 0; q < 8; q++) {
        int idx = tid + q*512;
        int r = idx >> 5, c4 = (idx & 31)*4;
        float4 v = make_float4(0.f,0.f,0.f,0.f);
        if (row0 + r < Nn) {
            float* mp = g_msum + (size_t)(row0 + r)*128 + c4;
            v = *(const float4*)mp;
            *(float4*)mp = make_float4(0.f,0.f,0.f,0.f);
            float inv = 1.0f / fmaxf(g_deg[row0 + r], 1.0f);
            v.x *= inv; v.y *= inv; v.z *= inv; v.w *= inv;
        }
        unsigned h[4], l[4];
        split_bf16(v.x, h[0], l[0]); split_bf16(v.y, h[1], l[1]);
        split_bf16(v.z, h[2], l[2]); split_bf16(v.w, h[3], l[3]);
        unsigned off = (unsigned)(r*136 + c4)*2u;
        *(uint2*)(smc + off)         = make_uint2(h[0]|(h[1]<<16), h[2]|(h[3]<<16));
        *(uint2*)(smc + 34816 + off) = make_uint2(l[0]|(l[1]<<16), l[2]|(l[3]<<16));
    }
    __syncthreads();
    hmma_gemm(sb, sb + 34816, sb + 139264, sb + 174080, m0, n0, lane, acc);
    __syncthreads();

    #pragma unroll
    for (int s = 0; s < 8; s++) {
        int col = n0 + s*8 + (lane & 3)*2;
        float v00 = silu_f(acc[s][0] + bb[col]);
        float v01 = silu_f(acc[s][1] + bb[col+1]);
        float v10 = silu_f(acc[s][2] + bb[col]);
        float v11 = silu_f(acc[s][3] + bb[col+1]);
        unsigned h0, l0, h1, l1;
        split_bf16(v00, h0, l0); split_bf16(v01, h1, l1);
        *(unsigned*)(smc + (rl*136 + col)*2)         = h0 | (h1 << 16);
        *(unsigned*)(smc + 34816 + (rl*136 + col)*2) = l0 | (l1 << 16);
        split_bf16(v10, h0, l0); split_bf16(v11, h1, l1);
        *(unsigned*)(smc + ((rl+8)*136 + col)*2)         = h0 | (h1 << 16);
        *(unsigned*)(smc + 34816 + ((rl+8)*136 + col)*2) = l0 | (l1 << 16);
    }
    __syncthreads();
    #pragma unroll
    for (int i = 0; i < 8; i++)
        #pragma unroll
        for (int j = 0; j < 4; j++) acc[i][j] = 0.f;
    hmma_gemm(sb, sb + 34816, sb + 69632, sb + 104448, m0, n0, lane, acc);
    #pragma unroll
    for (int s = 0; s < 8; s++) {
        int col = n0 + s*8 + (lane & 3)*2;
        acc[s][0] += bb[128+col]; acc[s][1] += bb[128+col+1];
        acc[s][2] += bb[128+col]; acc[s][3] += bb[128+col+1];
        int ra = row0 + rl, rb = ra + 8;
        if (ra < Nn) *(float2*)(g_feat + (size_t)ra*128 + col) = make_float2(acc[s][0], acc[s][1]);
        if (rb < Nn) *(float2*)(g_feat + (size_t)rb*128 + col) = make_float2(acc[s][2], acc[s][3]);
    }
    if (next < 0) return;

    __syncthreads();
    {
        const char* ah = (const char*)(g_Wbh + (size_t)(next*8 + 3)*17408);
        const char* al = (const char*)(g_Wbl + (size_t)(next*8 + 3)*17408);
        const char* bh = (const char*)(g_Wbh + (size_t)(next*8 + 4)*17408);
        const char* bl = (const char*)(g_Wbl + (size_t)(next*8 + 4)*17408);
        for (int i = tid; i < 2176; i += 512) {
            asm volatile("cp.async.cg.shared.global [%0], [%1], 16;"
                :: "r"(sb + 69632u + (unsigned)i*16u), "l"(ah + (size_t)i*16) : "memory");
            asm volatile("cp.async.cg.shared.global [%0], [%1], 16;"
                :: "r"(sb + 104448u + (unsigned)i*16u), "l"(al + (size_t)i*16) : "memory");
            asm volatile("cp.async.cg.shared.global [%0], [%1], 16;"
                :: "r"(sb + 139264u + (unsigned)i*16u), "l"(bh + (size_t)i*16) : "memory");
            asm volatile("cp.async.cg.shared.global [%0], [%1], 16;"
                :: "r"(sb + 174080u + (unsigned)i*16u), "l"(bl + (size_t)i*16) : "memory");
        }
        asm volatile("cp.async.commit_group;" ::: "memory");
    }
    #pragma unroll
    for (int s = 0; s < 8; s++) {
        int col = n0 + s*8 + (lane & 3)*2;
        unsigned h0, l0, h1, l1;
        split_bf16(acc[s][0], h0, l0); split_bf16(acc[s][1], h1, l1);
        *(unsigned*)(smc + (rl*136 + col)*2)         = h0 | (h1 << 16);
        *(unsigned*)(smc + 34816 + (rl*136 + col)*2) = l0 | (l1 << 16);
        split_bf16(acc[s][2], h0, l0); split_bf16(acc[s][3], h1, l1);
        *(unsigned*)(smc + ((rl+8)*136 + col)*2)         = h0 | (h1 << 16);
        *(unsigned*)(smc + 34816 + ((rl+8)*136 + col)*2) = l0 | (l1 << 16);
    }
    asm volatile("cp.async.wait_group 0;" ::: "memory");
    __syncthreads();

    #pragma unroll
    for (int i = 0; i < 8; i++)
        #pragma unroll
        for (int j = 0; j < 4; j++) acc[i][j] = 0.f;
    hmma_gemm(sb, sb + 34816, sb + 69632, sb + 104448, m0, n0, lane, acc);
    #pragma unroll
    for (int s = 0; s < 8; s++) {
        int col = n0 + s*8 + (lane & 3)*2;
        int ra = row0 + rl, rb = ra + 8;
        if (ra < Nn) *(float2*)(g_featA + (size_t)ra*128 + col) = make_float2(acc[s][0], acc[s][1]);
        if (rb < Nn) *(float2*)(g_featA + (size_t)rb*128 + col) = make_float2(acc[s][2], acc[s][3]);
    }
    #pragma unroll
    for (int i = 0; i < 8; i++)
        #pragma unroll
        for (int j = 0; j < 4; j++) acc[i][j] = 0.f;
    hmma_gemm(sb, sb + 34816, sb + 139264, sb + 174080, m0, n0, lane, acc);
    #pragma unroll
    for (int s = 0; s < 8; s++) {
        int col = n0 + s*8 + (lane & 3)*2;
        int ra = row0 + rl, rb = ra + 8;
        if (ra < Nn) *(float2*)(g_featB + (size_t)ra*128 + col) = make_float2(acc[s][0], acc[s][1]);
        if (rb < Nn) *(float2*)(g_featB + (size_t)rb*128 + col) = make_float2(acc[s][2], acc[s][3]);
    }
}

// ============ FUSED edge kernel: 256 threads, 64-edge tiles, 2 blocks/SM ============
// bytes: Ah 0 (17408) | Al 17408 (17408) | Wh 34816 (34816) | Wl 69632 (34816) |
// scal/pd-union 104448 (2048) | bh 106496 | bhp 107008 | bhs 107520 | w2p 108032 |
// w2s 108544 (1536) | ridx 110080 | cidx 110336 | wtl 110592 (2560) -> 113152
#define FU_SMEM 113152
__global__ void __launch_bounds__(256, 2)
edge_fused_mma(const float* __restrict__ bm2l,
               const float* __restrict__ Wm1tail, const float* __restrict__ bm1l,
               const float* __restrict__ bp1l, const float* __restrict__ Wp2l,
               const float* __restrict__ bp2l,
               const float* __restrict__ bs1l, const float* __restrict__ Ws2l,
               const float* __restrict__ bs2l, int layer) {
    extern __shared__ char smc[];
    unsigned sb = smem_u32(smc);
    float* scal = (float*)(smc + 104448);   // aliased with pd (disjoint live ranges)
    float* pd   = (float*)(smc + 104448);   // [2][64][4]
    float* bh   = (float*)(smc + 106496);
    float* bhp  = (float*)(smc + 107008);
    float* bhs  = (float*)(smc + 107520);
    float* w2p  = (float*)(smc + 108032);
    float* w2s  = (float*)(smc + 108544);
    int* ridx   = (int*)(smc + 110080);
    int* cidx   = (int*)(smc + 110336);
    float* wtl  = (float*)(smc + 110592);
    int tid = threadIdx.x, w = tid >> 5, lane = tid & 31;

    const char* Wm2h = (const char*)(g_Wbh + (size_t)(layer*8 + 0)*17408);
    const char* Wm2l = (const char*)(g_Wbl + (size_t)(layer*8 + 0)*17408);
    const char* Wp1h = (const char*)(g_Wbh + (size_t)(layer*8 + 1)*17408);
    const char* Wp1l = (const char*)(g_Wbl + (size_t)(layer*8 + 1)*17408);
    const char* Ws1h = (const char*)(g_Wbh + (size_t)(layer*8 + 2)*17408);
    const char* Ws1l = (const char*)(g_Wbl + (size_t)(layer*8 + 2)*17408);

    if (tid < 128) {
        bh[tid] = bm2l[tid]; bhp[tid] = bp1l[tid]; bhs[tid] = bs1l[tid];
        w2p[tid] = Wp2l[tid];
        w2s[tid*3+0] = Ws2l[tid*3+0]; w2s[tid*3+1] = Ws2l[tid*3+1]; w2s[tid*3+2] = Ws2l[tid*3+2];
    }
    for (int i = tid; i < 640; i += 256)
        wtl[i] = (i < 512) ? Wm1tail[i] : bm1l[i - 512];

    // 8 warps: m-groups 0..3 (16 rows each, 64 total), n-groups 0..1 (64 cols each)
    int m0 = (w & 3)*16, n0 = (w >> 2)*64;
    int ngrp = w >> 2;
    int rl = m0 + (lane >> 2);

    for (int t = blockIdx.x; t < NT; t += gridDim.x) {
        int e0 = t*64;
        __syncthreads();   // prev tile fully done (A/W/pd free)
        // async-load Wm2; hides under scal + h-build (+ partner block's compute)
        for (int i = tid; i < 2176; i += 256) {
            asm volatile("cp.async.cg.shared.global [%0], [%1], 16;"
                :: "r"(sb + 34816u + (unsigned)i*16u), "l"(Wm2h + (size_t)i*16) : "memory");
            asm volatile("cp.async.cg.shared.global [%0], [%1], 16;"
                :: "r"(sb + 69632u + (unsigned)i*16u), "l"(Wm2l + (size_t)i*16) : "memory");
        }
        asm volatile("cp.async.commit_group;" ::: "memory");
        if (tid < 64) {
            int r = g_er[e0 + tid], c = g_ec[e0 + tid];
            ridx[tid] = r; cidx[tid] = c;
            float dp0 = g_pos[r*3+0] - g_pos[c*3+0];
            float dp1 = g_pos[r*3+1] - g_pos[c*3+1];
            float dp2 = g_pos[r*3+2] - g_pos[c*3+2];
            float ip2 = 0.f;
            #pragma unroll
            for (int q = 4; q < 9; q++) ip2 += g_sh[r*9+q]*g_sh[c*9+q];
            scal[tid*4+0] = dp0*dp0 + dp1*dp1 + dp2*dp2;
            scal[tid*4+1] = g_sh[r*9+0]*g_sh[c*9+0];
            scal[tid*4+2] = g_sh[r*9+1]*g_sh[c*9+1] + g_sh[r*9+2]*g_sh[c*9+2] + g_sh[r*9+3]*g_sh[c*9+3];
            scal[tid*4+3] = ip2;
        }
        __syncthreads();
        // h-build: 64 edges x 32 float4-chunks
        #pragma unroll
        for (int q = 0; q < 8; q++) {
            int idx = tid + q*256;
            int e = idx >> 5, c4 = (idx & 31)*4;
            int r = ridx[e], c = cidx[e];
            float4 fa = *(const float4*)(g_featA + (size_t)r*128 + c4);
            float4 fb = *(const float4*)(g_featB + (size_t)c*128 + c4);
            float d2 = scal[e*4+0], i0 = scal[e*4+1], i1 = scal[e*4+2], i2 = scal[e*4+3];
            float hv[4];
            hv[0] = silu_f(fa.x + fb.x + d2*wtl[c4+0] + i0*wtl[128+c4+0] + i1*wtl[256+c4+0] + i2*wtl[384+c4+0] + wtl[512+c4+0]);
            hv[1] = silu_f(fa.y + fb.y + d2*wtl[c4+1] + i0*wtl[128+c4+1] + i1*wtl[256+c4+1] + i2*wtl[384+c4+1] + wtl[512+c4+1]);
            hv[2] = silu_f(fa.z + fb.z + d2*wtl[c4+2] + i0*wtl[128+c4+2] + i1*wtl[256+c4+2] + i2*wtl[384+c4+2] + wtl[512+c4+2]);
            hv[3] = silu_f(fa.w + fb.w + d2*wtl[c4+3] + i0*wtl[128+c4+3] + i1*wtl[256+c4+3] + i2*wtl[384+c4+3] + wtl[512+c4+3]);
            unsigned h[4], l[4];
            #pragma unroll
            for (int j = 0; j < 4; j++) split_bf16(hv[j], h[j], l[j]);
            unsigned off = (unsigned)(e*136 + c4)*2u;
            *(uint2*)(smc + off)         = make_uint2(h[0]|(h[1]<<16), h[2]|(h[3]<<16));
            *(uint2*)(smc + 17408 + off) = make_uint2(l[0]|(l[1]<<16), l[2]|(l[3]<<16));
        }
        asm volatile("cp.async.wait_group 0;" ::: "memory");   // Wm2 ready
        __syncthreads();

        // GEMM1: m = h @ Wm2
        float acc[8][4];
        #pragma unroll
        for (int i = 0; i < 8; i++)
            #pragma unroll
            for (int j = 0; j < 4; j++) acc[i][j] = 0.f;
        hmma_gemm(sb, sb + 17408, sb + 34816, sb + 69632, m0, n0, lane, acc);
        __syncthreads();   // A + W reads done

        // async-load Wp1; hides under m epilogue
        for (int i = tid; i < 2176; i += 256) {
            asm volatile("cp.async.cg.shared.global [%0], [%1], 16;"
                :: "r"(sb + 34816u + (unsigned)i*16u), "l"(Wp1h + (size_t)i*16) : "memory");
            asm volatile("cp.async.cg.shared.global [%0], [%1], 16;"
                :: "r"(sb + 69632u + (unsigned)i*16u), "l"(Wp1l + (size_t)i*16) : "memory");
        }
        asm volatile("cp.async.commit_group;" ::: "memory");
        // m epilogue: split into A
        #pragma unroll
        for (int s = 0; s < 8; s++) {
            int col = n0 + s*8 + (lane & 3)*2;
            float v00 = silu_f(acc[s][0] + bh[col]);
            float v01 = silu_f(acc[s][1] + bh[col+1]);
            float v10 = silu_f(acc[s][2] + bh[col]);
            float v11 = silu_f(acc[s][3] + bh[col+1]);
            unsigned h0, l0, h1, l1;
            split_bf16(v00, h0, l0); split_bf16(v01, h1, l1);
            *(unsigned*)(smc + (rl*136 + col)*2)         = h0 | (h1 << 16);
            *(unsigned*)(smc + 17408 + (rl*136 + col)*2) = l0 | (l1 << 16);
            split_bf16(v10, h0, l0); split_bf16(v11, h1, l1);
            *(unsigned*)(smc + ((rl+8)*136 + col)*2)         = h0 | (h1 << 16);
            *(unsigned*)(smc + 17408 + ((rl+8)*136 + col)*2) = l0 | (l1 << 16);
        }
        asm volatile("cp.async.wait_group 0;" ::: "memory");   // Wp1 ready
        __syncthreads();

        // GEMM2: p = m @ Wp1
        float accp[8][4];
        #pragma unroll
        for (int i = 0; i < 8; i++)
            #pragma unroll
            for (int j = 0; j < 4; j++) accp[i][j] = 0.f;
        hmma_gemm(sb, sb + 17408, sb + 34816, sb + 69632, m0, n0, lane, accp);
        __syncthreads();   // W reads done

        // async-load Ws1; hides under p epilogue
        for (int i = tid; i < 2176; i += 256) {
            asm volatile("cp.async.cg.shared.global [%0], [%1], 16;"
                :: "r"(sb + 34816u + (unsigned)i*16u), "l"(Ws1h + (size_t)i*16) : "memory");
            asm volatile("cp.async.cg.shared.global [%0], [%1], 16;"
                :: "r"(sb + 69632u + (unsigned)i*16u), "l"(Ws1l + (size_t)i*16) : "memory");
        }
        asm volatile("cp.async.commit_group;" ::: "memory");
        {
            float pr0 = 0.f, pr1 = 0.f;
            #pragma unroll
            for (int s = 0; s < 8; s++) {
                int col = n0 + s*8 + (lane & 3)*2;
                pr0 = fmaf(silu_f(accp[s][0] + bhp[col]),   w2p[col],
                      fmaf(silu_f(accp[s][1] + bhp[col+1]), w2p[col+1], pr0));
                pr1 = fmaf(silu_f(accp[s][2] + bhp[col]),   w2p[col],
                      fmaf(silu_f(accp[s][3] + bhp[col+1]), w2p[col+1], pr1));
            }
            #pragma unroll
            for (int off = 1; off <= 2; off <<= 1) {
                pr0 += __shfl_xor_sync(0xffffffffu, pr0, off);
                pr1 += __shfl_xor_sync(0xffffffffu, pr1, off);
            }
            if ((lane & 3) == 0) {
                pd[ngrp*256 + rl*4 + 0] = pr0;
                pd[ngrp*256 + (rl+8)*4 + 0] = pr1;
            }
        }
        asm volatile("cp.async.wait_group 0;" ::: "memory");   // Ws1 ready
        __syncthreads();

        // GEMM3: s = m @ Ws1
        float accs[8][4];
        #pragma unroll
        for (int i = 0; i < 8; i++)
            #pragma unroll
            for (int j = 0; j < 4; j++) accs[i][j] = 0.f;
        hmma_gemm(sb, sb + 17408, sb + 34816, sb + 69632, m0, n0, lane, accs);
        {
            float s0r0 = 0.f, s1r0 = 0.f, s2r0 = 0.f;
            float s0r1 = 0.f, s1r1 = 0.f, s2r1 = 0.f;
            #pragma unroll
            for (int s = 0; s < 8; s++) {
                int col = n0 + s*8 + (lane & 3)*2;
                float g00 = silu_f(accs[s][0] + bhs[col]);
                float g01 = silu_f(accs[s][1] + bhs[col+1]);
                float g10 = silu_f(accs[s][2] + bhs[col]);
                float g11 = silu_f(accs[s][3] + bhs[col+1]);
                s0r0 = fmaf(g00, w2s[col*3+0], fmaf(g01, w2s[(col+1)*3+0], s0r0));
                s1r0 = fmaf(g00, w2s[col*3+1], fmaf(g01, w2s[(col+1)*3+1], s1r0));
                s2r0 = fmaf(g00, w2s[col*3+2], fmaf(g01, w2s[(col+1)*3+2], s2r0));
                s0r1 = fmaf(g10, w2s[col*3+0], fmaf(g11, w2s[(col+1)*3+0], s0r1));
                s1r1 = fmaf(g10, w2s[col*3+1], fmaf(g11, w2s[(col+1)*3+1], s1r1));
                s2r1 = fmaf(g10, w2s[col*3+2], fmaf(g11, w2s[(col+1)*3+2], s2r1));
            }
            #pragma unroll
            for (int off = 1; off <= 2; off <<= 1) {
                s0r0 += __shfl_xor_sync(0xffffffffu, s0r0, off);
                s1r0 += __shfl_xor_sync(0xffffffffu, s1r0, off);
                s2r0 += __shfl_xor_sync(0xffffffffu, s2r0, off);
                s0r1 += __shfl_xor_sync(0xffffffffu, s0r1, off);
                s1r1 += __shfl_xor_sync(0xffffffffu, s1r1, off);
                s2r1 += __shfl_xor_sync(0xffffffffu, s2r1, off);
            }
            if ((lane & 3) == 0) {
                float* p0 = pd + ngrp*256 + rl*4;
                p0[1] = s0r0; p0[2] = s1r0; p0[3] = s2r0;
                float* p1 = pd + ngrp*256 + (rl+8)*4;
                p1[1] = s0r1; p1[2] = s1r1; p1[3] = s2r1;
            }
        }
        __syncthreads();
        // scatters + msum walk
        if (tid < 64) {
            int r = ridx[tid], c = cidx[tid];
            float psc = pd[tid*4+0] + pd[256 + tid*4+0] + bp2l[0];
            float s0  = pd[tid*4+1] + pd[256 + tid*4+1] + bs2l[0];
            float s1  = pd[tid*4+2] + pd[256 + tid*4+2] + bs2l[1];
            float s2  = pd[tid*4+3] + pd[256 + tid*4+3] + bs2l[2];
            float dp0 = g_pos[r*3+0] - g_pos[c*3+0];
            float dp1 = g_pos[r*3+1] - g_pos[c*3+1];
            float dp2 = g_pos[r*3+2] - g_pos[c*3+2];
            atomicAdd(&g_psum[r*3+0], dp0*psc);
            atomicAdd(&g_psum[r*3+1], dp1*psc);
            atomicAdd(&g_psum[r*3+2], dp2*psc);
            #pragma unroll
            for (int q = 0; q < 9; q++) {
                float diff = g_sh[r*9+q] - g_sh[c*9+q];
                atomicAdd(&g_ssum[r*9+q], diff * ((q == 0) ? s0 : (q < 4) ? s1 : s2));
            }
        }
        {
            int c = tid & 127, seg = tid >> 7;
            int eb = seg*32;
            float agg = 0.f;
            int ar = ridx[eb];
            for (int e = eb; e < eb + 32; e++) {
                ush hi = *(const ush*)(smc + (e*136 + c)*2);
                ush lo = *(const ush*)(smc + 17408 + (e*136 + c)*2);
                float v = __bfloat162float(__ushort_as_bfloat16(hi))
                        + __bfloat162float(__ushort_as_bfloat16(lo));
                int r = ridx[e];
                if (r != ar) { atomicAdd(&g_msum[(size_t)ar*128 + c], agg); agg = v; ar = r; }
                else agg += v;
            }
            atomicAdd(&g_msum[(size_t)ar*128 + c], agg);
        }
    }
}

// posh also zeroes psum/ssum for the next layer
__global__ void posh_kernel() {
    int i = blockIdx.x*256 + threadIdx.x;
    if (i >= Nn) return;
    float inv = 1.0f / fmaxf(g_deg[i], 1.0f);
    #pragma unroll
    for (int q = 0; q < 3; q++) {
        g_pos[i*3+q] += g_psum[i*3+q]*inv;
        g_psum[i*3+q] = 0.0f;
    }
    #pragma unroll
    for (int q = 0; q < 9; q++) {
        g_sh[i*9+q] += g_ssum[i*9+q]*inv;
        g_ssum[i*9+q] = 0.0f;
    }
}
__global__ void pool_kernel(const int* __restrict__ batch) {
    int idx = blockIdx.x*256 + threadIdx.x;
    if (idx >= Nn*140) return;
    int i = idx / 140, c = idx % 140;
    float v;
    if (c < 128)      v = g_feat[(size_t)i*128 + c];
    else if (c < 131) v = g_pos[i*3 + (c - 128)];
    else              v = g_sh[i*9 + (c - 131)];
    atomicAdd(&g_pool[batch[i]*140 + c], v);
}
__global__ void pred_kernel(const float* __restrict__ Wpred, const float* __restrict__ bpred,
                            float* __restrict__ out) {
    int g = blockIdx.x, lane = threadIdx.x;
    float s = 0.f;
    for (int c = lane; c < 140; c += 32)
        s = fmaf(g_pool[g*140 + c], Wpred[c], s);
    #pragma unroll
    for (int off = 16; off > 0; off >>= 1)
        s += __shfl_xor_sync(0xffffffffu, s, off);
    if (lane == 0) out[g] = s + bpred[0];
}

extern "C" void kernel_launch(void* const* d_in, const int* in_sizes, int n_in,
                              void* d_out, int out_size) {
    const int*   atoms = (const int*)d_in[0];
    const int*   ei    = (const int*)d_in[1];
    const int*   batch = (const int*)d_in[2];
    const float* pos   = (const float*)d_in[3];
    const float* emb   = (const float*)d_in[4];
    const float* Wsi1  = (const float*)d_in[5];  const float* bsi1  = (const float*)d_in[6];
    const float* Wsi2  = (const float*)d_in[7];  const float* bsi2  = (const float*)d_in[8];
    const float* WsiC1 = (const float*)d_in[9];  const float* bsiC1 = (const float*)d_in[10];
    const float* WsiC2 = (const float*)d_in[11]; const float* bsiC2 = (const float*)d_in[12];
    const float* Wm1   = (const float*)d_in[13]; const float* bm1   = (const float*)d_in[14];
    const float* Wm2   = (const float*)d_in[15]; const float* bm2   = (const float*)d_in[16];
    const float* Wp1   = (const float*)d_in[17]; const float* bp1   = (const float*)d_in[18];
    const float* Wp2   = (const float*)d_in[19]; const float* bp2   = (const float*)d_in[20];
    const float* Wn1   = (const float*)d_in[21]; const float* bn1   = (const float*)d_in[22];
    const float* Wn2   = (const float*)d_in[23]; const float* bn2   = (const float*)d_in[24];
    const float* Ws1   = (const float*)d_in[25]; const float* bs1   = (const float*)d_in[26];
    const float* Ws2   = (const float*)d_in[27]; const float* bs2   = (const float*)d_in[28];
    const float* Wpred = (const float*)d_in[29]; const float* bpred = (const float*)d_in[30];
    float* out = (float*)d_out;

    cudaFuncSetAttribute(featab_mma, cudaFuncAttributeMaxDynamicSharedMemorySize, FABM_SMEM);
    cudaFuncSetAttribute(nodeup_mma, cudaFuncAttributeMaxDynamicSharedMemorySize, NUM_SMEM);
    cudaFuncSetAttribute(edge_fused_mma, cudaFuncAttributeMaxDynamicSharedMemorySize, FU_SMEM);

    void *p_msum, *p_psum, *p_ssum, *p_deg, *p_com, *p_cnt, *p_pool, *p_pos, *p_cur;
    cudaGetSymbolAddress(&p_msum, g_msum);
    cudaGetSymbolAddress(&p_psum, g_psum);
    cudaGetSymbolAddress(&p_ssum, g_ssum);
    cudaGetSymbolAddress(&p_deg,  g_deg);
    cudaGetSymbolAddress(&p_com,  g_com);
    cudaGetSymbolAddress(&p_cnt,  g_cnt);
    cudaGetSymbolAddress(&p_pool, g_pool);
    cudaGetSymbolAddress(&p_pos,  g_pos);
    cudaGetSymbolAddress(&p_cur,  g_cursor);

    cudaMemsetAsync(p_deg,  0, Nn*4, 0);
    cudaMemsetAsync(p_com,  0, Gg*3*4, 0);
    cudaMemsetAsync(p_cnt,  0, Gg*4, 0);
    cudaMemsetAsync(p_ssum, 0, Nn*9*4, 0);
    cudaMemsetAsync(p_psum, 0, Nn*3*4, 0);
    cudaMemsetAsync(p_msum, 0, (size_t)Nn*128*4, 0);
    cudaMemsetAsync(p_pool, 0, Gg*140*4, 0);
    cudaMemsetAsync(p_cur,  0, Nn*4, 0);
    cudaMemcpyAsync(p_pos, pos, Nn*3*4, cudaMemcpyDeviceToDevice, 0);

    wprep_kernel<<<40, 256>>>(Wm2, Wp1, Ws1, Wm1, Wn1, Wn2);
    node_init_kernel<<<(Nn*128)/256, 256>>>(atoms, emb);
    com_kernel<<<(Nn + 255)/256, 256>>>(batch);
    deg_kernel<<<(Ee + 255)/256, 256>>>(ei);
    scan_kernel<<<1, 256>>>();
    sortscatter_kernel<<<(Ee + 255)/256, 256>>>(ei);
    vocab_kernel<<<10, 128>>>(emb, Wsi1, WsiC1, bsiC1, WsiC2, bsiC2);
    edge_init_kernel<<<Ee/8, 256>>>(atoms, Wsi1, bsi1, Wsi2, bsi2);
    sh_init_kernel<<<(Nn + 255)/256, 256>>>(atoms, batch);

    int gridNM = (Nn + 127)/128;   // 79

    featab_mma<<<gridNM, 512, FABM_SMEM>>>(0);

    for (int l = 0; l < Ll; l++) {
        edge_fused_mma<<<296, 256, FU_SMEM>>>(
            bm2 + l*128,
            Wm1 + ((size_t)l*260 + 256)*128, bm1 + l*128,
            bp1 + l*128, Wp2 + l*128, bp2 + l,
            bs1 + l*128, Ws2 + l*384, bs2 + l*3, l);

        posh_kernel<<<(Nn + 255)/256, 256>>>();

        nodeup_mma<<<gridNM, 512, NUM_SMEM>>>(bn1 + l*128, bn2 + l*128, l,
                                              (l + 1 < Ll) ? (l + 1) : -1);
    }

    pool_kernel<<<(Nn*140 + 255)/256, 256>>>(batch);
    pred_kernel<<<Gg, 32>>>(Wpred, bpred, out);
}

// round 17
// speedup vs baseline: 1.1793x; 1.0308x over previous
#include <cuda_runtime.h>
#include <cuda_bf16.h>
#include <cstdint>
#include <math.h>

#define Nn 10000
#define Ee 160000
#define Gg 100
#define Ll 5
#define NT 2500   // 64-edge tiles (edge kernel)
#define NTN 313   // 32-row tiles (node kernel)

typedef unsigned long long u64;
typedef unsigned short ush;

__device__ float g_feat [Nn*128];
__device__ float g_featA[Nn*128];
__device__ float g_featB[Nn*128];
__device__ float g_sh   [Nn*9];
__device__ float g_pos  [Nn*3];
__device__ float g_msum [Nn*128];
__device__ float g_psum [Nn*3];
__device__ float g_ssum [Nn*9];
__device__ float g_deg  [Nn];
__device__ float g_com  [Gg*3];
__device__ float g_cnt  [Gg];
__device__ float g_P1   [10*128];
__device__ float g_P2   [10*128];
__device__ float g_cmsg [10];
__device__ float g_pool [Gg*140];
__device__ int   g_off  [Nn];
__device__ int   g_cursor[Nn];
__device__ int   g_er   [Ee];
__device__ int   g_ec   [Ee];
__device__ ush   g_Wbh [40*17408];          // [l*8+slot][n*136+k] hi
__device__ ush   g_Wbl [40*17408];          // lo

__device__ __forceinline__ float silu_f(float x) { return x / (1.0f + __expf(-x)); }

__device__ __forceinline__ void sph2(float vx, float vy, float vz, float* o) {
    const float S3 = 1.7320508075688772f, HS3 = 0.8660254037844386f;
    float r = sqrtf(vx*vx + vy*vy + vz*vz);
    float inv = 1.0f / fmaxf(r, 1e-12f);
    float x = vx*inv, y = vy*inv, z = vz*inv;
    o[0] = S3*x*z; o[1] = S3*x*y; o[2] = y*y - 0.5f*(x*x + z*z);
    o[3] = S3*y*z; o[4] = HS3*(z*z - x*x);
}

// ---- HMMA helpers ----
__device__ __forceinline__ unsigned smem_u32(const void* p) {
    unsigned a; asm("{ .reg .u64 t; cvta.to.shared.u64 t, %1; cvt.u32.u64 %0, t; }" : "=r"(a) : "l"(p));
    return a;
}
__device__ __forceinline__ void ldsm4(unsigned addr, unsigned* r) {
    asm volatile("ldmatrix.sync.aligned.m8n8.x4.shared.b16 {%0,%1,%2,%3}, [%4];"
        : "=r"(r[0]), "=r"(r[1]), "=r"(r[2]), "=r"(r[3]) : "r"(addr));
}
__device__ __forceinline__ void mma_bf16(float* d, const unsigned* a, unsigned b0, unsigned b1) {
    asm volatile("mma.sync.aligned.m16n8k16.row.col.f32.bf16.bf16.f32 "
        "{%0,%1,%2,%3},{%4,%5,%6,%7},{%8,%9},{%0,%1,%2,%3};"
        : "+f"(d[0]), "+f"(d[1]), "+f"(d[2]), "+f"(d[3])
        : "r"(a[0]), "r"(a[1]), "r"(a[2]), "r"(a[3]), "r"(b0), "r"(b1));
}
__device__ __forceinline__ void split_bf16(float v, unsigned& h, unsigned& l) {
    __nv_bfloat16 hb = __float2bfloat16(v);
    h = (unsigned)__bfloat16_as_ushort(hb);
    l = (unsigned)__bfloat16_as_ushort(__float2bfloat16(v - __bfloat162float(hb)));
}

// split-bf16 GEMM core: rows m0..+15 x cols n0..+63, K=128; A/B ush stride 136 (272 B)
__device__ __forceinline__ void hmma_gemm(unsigned aH, unsigned aL, unsigned bH, unsigned bL,
                                          int m0, int n0, int lane, float acc[8][4]) {
    unsigned aoff = (unsigned)((m0 + (lane & 15))*272 + (lane >> 4)*16);
    unsigned boff = (unsigned)((n0 + (lane & 15))*272 + (lane >> 4)*16);
    #pragma unroll
    for (int kk = 0; kk < 8; kk++) {
        unsigned kb = kk*32;
        unsigned Ah[4], Al[4];
        ldsm4(aH + aoff + kb, Ah);
        ldsm4(aL + aoff + kb, Al);
        #pragma unroll
        for (int t = 0; t < 4; t++) {
            unsigned bo = boff + t*16*272 + kb;
            unsigned Bh[4], Bl[4];
            ldsm4(bH + bo, Bh);
            ldsm4(bL + bo, Bl);
            mma_bf16(acc[2*t],   Ah, Bh[0], Bh[2]);
            mma_bf16(acc[2*t],   Ah, Bl[0], Bl[2]);
            mma_bf16(acc[2*t],   Al, Bh[0], Bh[2]);
            mma_bf16(acc[2*t+1], Ah, Bh[1], Bh[3]);
            mma_bf16(acc[2*t+1], Ah, Bl[1], Bl[3]);
            mma_bf16(acc[2*t+1], Al, Bh[1], Bh[3]);
        }
    }
}

// 16x32 variant: rows m0..+15 x cols n0..+31 (accumulates; caller zeroes)
__device__ __forceinline__ void hmma_g16n32(unsigned aH, unsigned aL, unsigned bH, unsigned bL,
                                            int m0, int n0, int lane, float acc[4][4]) {
    unsigned aoff = (unsigned)((m0 + (lane & 15))*272 + (lane >> 4)*16);
    unsigned boff = (unsigned)((n0 + (lane & 15))*272 + (lane >> 4)*16);
    #pragma unroll
    for (int kk = 0; kk < 8; kk++) {
        unsigned kb = kk*32;
        unsigned Ah[4], Al[4];
        ldsm4(aH + aoff + kb, Ah);
        ldsm4(aL + aoff + kb, Al);
        #pragma unroll
        for (int t = 0; t < 2; t++) {
            unsigned bo = boff + t*16*272 + kb;
            unsigned Bh[4], Bl[4];
            ldsm4(bH + bo, Bh);
            ldsm4(bL + bo, Bl);
            mma_bf16(acc[2*t],   Ah, Bh[0], Bh[2]);
            mma_bf16(acc[2*t],   Ah, Bl[0], Bl[2]);
            mma_bf16(acc[2*t],   Al, Bh[0], Bh[2]);
            mma_bf16(acc[2*t+1], Ah, Bh[1], Bh[3]);
            mma_bf16(acc[2*t+1], Ah, Bl[1], Bl[3]);
            mma_bf16(acc[2*t+1], Al, Bh[1], Bh[3]);
        }
    }
}

// weights -> split-bf16 [n][k] stride-136 tiles
// slot: 0 Wm2, 1 Wp1, 2 Ws1, 3 Wa, 4 Wb, 5 W5, 6 W6, 7 W7
__global__ void wprep_kernel(const float* __restrict__ Wm2, const float* __restrict__ Wp1,
                             const float* __restrict__ Ws1, const float* __restrict__ Wm1,
                             const float* __restrict__ Wn1, const float* __restrict__ Wn2) {
    int bid = blockIdx.x, l = bid >> 3, slot = bid & 7;
    const float* src;
    switch (slot) {
        case 0: src = Wm2 + (size_t)l*16384;              break;
        case 1: src = Wp1 + (size_t)l*16384;              break;
        case 2: src = Ws1 + (size_t)l*16384;              break;
        case 3: src = Wm1 + (size_t)l*260*128;            break;
        case 4: src = Wm1 + ((size_t)l*260 + 128)*128;    break;
        case 5: src = Wn1 + (size_t)l*256*128;            break;
        case 6: src = Wn1 + ((size_t)l*256 + 128)*128;    break;
        default:src = Wn2 + (size_t)l*16384;              break;
    }
    ush* dh = g_Wbh + (size_t)bid*17408;
    ush* dl = g_Wbl + (size_t)bid*17408;
    for (int o = threadIdx.x; o < 16384; o += 256) {
        int k = o >> 7, n = o & 127;
        unsigned h, lo;
        split_bf16(src[k*128 + n], h, lo);
        dh[n*136 + k] = (ush)h;
        dl[n*136 + k] = (ush)lo;
    }
}

// ---- init kernels ----
__global__ void node_init_kernel(const int* __restrict__ atoms, const float* __restrict__ emb) {
    int idx = blockIdx.x*256 + threadIdx.x;
    g_feat[idx] = emb[atoms[idx >> 7]*128 + (idx & 127)];
}
__global__ void com_kernel(const int* __restrict__ batch) {
    int i = blockIdx.x*256 + threadIdx.x;
    if (i >= Nn) return;
    int b = batch[i];
    atomicAdd(&g_com[b*3+0], g_pos[i*3+0]);
    atomicAdd(&g_com[b*3+1], g_pos[i*3+1]);
    atomicAdd(&g_com[b*3+2], g_pos[i*3+2]);
    atomicAdd(&g_cnt[b], 1.0f);
}
__global__ void deg_kernel(const int* __restrict__ ei) {
    int e = blockIdx.x*256 + threadIdx.x;
    if (e < Ee) atomicAdd(&g_deg[ei[e]], 1.0f);
}
__global__ void scan_kernel() {
    __shared__ int part[256];
    int tid = threadIdx.x;
    int lo = tid*40, hi = (lo + 40 < Nn) ? lo + 40 : Nn;
    int s = 0;
    for (int i = lo; i < hi; i++) s += (int)g_deg[i];
    part[tid] = s;
    __syncthreads();
    for (int off = 1; off < 256; off <<= 1) {
        int v = part[tid] + ((tid >= off) ? part[tid - off] : 0);
        __syncthreads(); part[tid] = v; __syncthreads();
    }
    int base = (tid > 0) ? part[tid - 1] : 0;
    for (int i = lo; i < hi; i++) { g_off[i] = base; base += (int)g_deg[i]; }
}
__global__ void sortscatter_kernel(const int* __restrict__ ei) {
    int e = blockIdx.x*256 + threadIdx.x;
    if (e >= Ee) return;
    int r = ei[e], c = ei[Ee + e];
    int p = g_off[r] + atomicAdd(&g_cursor[r], 1);
    g_er[p] = r; g_ec[p] = c;
}
__global__ void vocab_kernel(const float* __restrict__ emb, const float* __restrict__ Wsi1,
                             const float* __restrict__ WsiC1, const float* __restrict__ bsiC1,
                             const float* __restrict__ WsiC2, const float* __restrict__ bsiC2) {
    __shared__ float es[128], redv[128];
    int v = blockIdx.x, j = threadIdx.x;
    es[j] = emb[v*128 + j];
    __syncthreads();
    float p1 = 0.f, p2 = 0.f, hc = 0.f;
    for (int k = 0; k < 128; k++) {
        float e = es[k];
        p1 = fmaf(e, Wsi1[(1 + k)*128 + j], p1);
        p2 = fmaf(e, Wsi1[(129 + k)*128 + j], p2);
        hc = fmaf(e, WsiC1[k*128 + j], hc);
    }
    g_P1[v*128 + j] = p1; g_P2[v*128 + j] = p2;
    redv[j] = silu_f(hc + bsiC1[j]) * WsiC2[j*3 + 2];
    __syncthreads();
    for (int s = 64; s > 0; s >>= 1) {
        if (j < s) redv[j] += redv[j + s];
        __syncthreads();
    }
    if (j == 0) g_cmsg[v] = redv[0] + bsiC2[2];
}
__global__ void edge_init_kernel(const int* __restrict__ atoms,
                                 const float* __restrict__ Wsi1, const float* __restrict__ bsi1,
                                 const float* __restrict__ Wsi2, const float* __restrict__ bsi2) {
    int e = blockIdx.x*8 + (threadIdx.x >> 5);
    int lane = threadIdx.x & 31;
    int r = g_er[e], c = g_ec[e];
    float dp0 = g_pos[r*3+0] - g_pos[c*3+0];
    float dp1 = g_pos[r*3+1] - g_pos[c*3+1];
    float dp2 = g_pos[r*3+2] - g_pos[c*3+2];
    float dist = sqrtf(dp0*dp0 + dp1*dp1 + dp2*dp2);
    int ar = atoms[r], ac = atoms[c];
    float partial = 0.f;
    #pragma unroll
    for (int q = 0; q < 4; q++) {
        int d = lane + q*32;
        partial = fmaf(silu_f(dist*Wsi1[d] + g_P1[ar*128 + d] + g_P2[ac*128 + d] + bsi1[d]),
                       Wsi2[d*3 + 2], partial);
    }
    #pragma unroll
    for (int off = 16; off > 0; off >>= 1)
        partial += __shfl_xor_sync(0xffffffffu, partial, off);
    if (lane == 0) {
        float msg2 = partial + bsi2[2];
        float y2[5];
        sph2(dp0, dp1, dp2, y2);
        #pragma unroll
        for (int q = 0; q < 5; q++)
            atomicAdd(&g_ssum[r*9 + 4 + q], y2[q]*msg2);
    }
}
__global__ void sh_init_kernel(const int* __restrict__ atoms, const int* __restrict__ batch) {
    int i = blockIdx.x*256 + threadIdx.x;
    if (i >= Nn) return;
    float dg = fmaxf(g_deg[i], 1.0f);
    int b = batch[i];
    float cn = fmaxf(g_cnt[b], 1.0f);
    float y2[5];
    sph2(g_pos[i*3+0] - g_com[b*3+0]/cn, g_pos[i*3+1] - g_com[b*3+1]/cn,
         g_pos[i*3+2] - g_com[b*3+2]/cn, y2);
    float cm = g_cmsg[atoms[i]];
    #pragma unroll
    for (int q = 0; q < 4; q++) g_sh[i*9 + q] = 0.0f;
    #pragma unroll
    for (int q = 0; q < 5; q++)
        g_sh[i*9 + 4 + q] = g_ssum[i*9 + 4 + q]/dg + cm*y2[q];
    #pragma unroll
    for (int q = 0; q < 9; q++) g_ssum[i*9 + q] = 0.0f;
}

// ============ featAB via HMMA (layer 0 only, proven) ============
#define FABM_SMEM 208896
__global__ void __launch_bounds__(512, 1)
featab_mma(int layer) {
    extern __shared__ char smc[];
    unsigned sb = smem_u32(smc);
    int tid = threadIdx.x, w = tid >> 5, lane = tid & 31;
    int row0 = blockIdx.x * 128;

    {
        const uint4* ah = (const uint4*)(g_Wbh + (size_t)(layer*8 + 3)*17408);
        const uint4* al = (const uint4*)(g_Wbl + (size_t)(layer*8 + 3)*17408);
        const uint4* bh = (const uint4*)(g_Wbh + (size_t)(layer*8 + 4)*17408);
        const uint4* bl = (const uint4*)(g_Wbl + (size_t)(layer*8 + 4)*17408);
        uint4* dah = (uint4*)(smc + 69632);
        uint4* dal = (uint4*)(smc + 104448);
        uint4* dbh = (uint4*)(smc + 139264);
        uint4* dbl = (uint4*)(smc + 174080);
        for (int i = tid; i < 2176; i += 512) {
            dah[i] = ah[i]; dal[i] = al[i]; dbh[i] = bh[i]; dbl[i] = bl[i];
        }
    }
    #pragma unroll
    for (int q = 0; q < 8; q++) {
        int idx = tid + q*512;
        int r = idx >> 5, c4 = (idx & 31)*4;
        float4 v = make_float4(0.f,0.f,0.f,0.f);
        if (row0 + r < Nn) v = *(const float4*)(g_feat + (size_t)(row0 + r)*128 + c4);
        unsigned h[4], l[4];
        split_bf16(v.x, h[0], l[0]); split_bf16(v.y, h[1], l[1]);
        split_bf16(v.z, h[2], l[2]); split_bf16(v.w, h[3], l[3]);
        unsigned off = (unsigned)(r*136 + c4)*2u;
        *(uint2*)(smc + off)         = make_uint2(h[0]|(h[1]<<16), h[2]|(h[3]<<16));
        *(uint2*)(smc + 34816 + off) = make_uint2(l[0]|(l[1]<<16), l[2]|(l[3]<<16));
    }
    __syncthreads();

    int m0 = (w & 7)*16, n0 = (w >> 3)*64;
    int rl = m0 + (lane >> 2);
    float acc[8][4];
    #pragma unroll
    for (int i = 0; i < 8; i++)
        #pragma unroll
        for (int j = 0; j < 4; j++) acc[i][j] = 0.f;
    hmma_gemm(sb, sb + 34816, sb + 69632, sb + 104448, m0, n0, lane, acc);
    #pragma unroll
    for (int s = 0; s < 8; s++) {
        int col = n0 + s*8 + (lane & 3)*2;
        int ra = row0 + rl, rb = ra + 8;
        if (ra < Nn) *(float2*)(g_featA + (size_t)ra*128 + col) = make_float2(acc[s][0], acc[s][1]);
        if (rb < Nn) *(float2*)(g_featA + (size_t)rb*128 + col) = make_float2(acc[s][2], acc[s][3]);
    }
    #pragma unroll
    for (int i = 0; i < 8; i++)
        #pragma unroll
        for (int j = 0; j < 4; j++) acc[i][j] = 0.f;
    hmma_gemm(sb, sb + 34816, sb + 139264, sb + 174080, m0, n0, lane, acc);
    #pragma unroll
    for (int s = 0; s < 8; s++) {
        int col = n0 + s*8 + (lane & 3)*2;
        int ra = row0 + rl, rb = ra + 8;
        if (ra < Nn) *(float2*)(g_featB + (size_t)ra*128 + col) = make_float2(acc[s][0], acc[s][1]);
        if (rb < Nn) *(float2*)(g_featB + (size_t)rb*128 + col) = make_float2(acc[s][2], acc[s][3]);
    }
}

// ============ node update, 256 threads, 32-row tiles, 2 blocks/SM ============
// bytes: Ah 0 (8704) | Al 8704 (8704) | Wh 17408 (34816) | Wl 52224 (34816) |
// bb 87040 (1024) -> 88064
#define NU2_SMEM 88064
__global__ void __launch_bounds__(256, 2)
nodeup_mma2(const float* __restrict__ b1, const float* __restrict__ b2, int layer, int next) {
    extern __shared__ char smc[];
    unsigned sb = smem_u32(smc);
    float* bb = (float*)(smc + 87040);
    int tid = threadIdx.x, w = tid >> 5, lane = tid & 31;

    const char* W5h = (const char*)(g_Wbh + (size_t)(layer*8 + 5)*17408);
    const char* W5l = (const char*)(g_Wbl + (size_t)(layer*8 + 5)*17408);
    const char* W6h = (const char*)(g_Wbh + (size_t)(layer*8 + 6)*17408);
    const char* W6l = (const char*)(g_Wbl + (size_t)(layer*8 + 6)*17408);
    const char* W7h = (const char*)(g_Wbh + (size_t)(layer*8 + 7)*17408);
    const char* W7l = (const char*)(g_Wbl + (size_t)(layer*8 + 7)*17408);
    const char* Wah = (next >= 0) ? (const char*)(g_Wbh + (size_t)(next*8 + 3)*17408) : 0;
    const char* Wal = (next >= 0) ? (const char*)(g_Wbl + (size_t)(next*8 + 3)*17408) : 0;
    const char* Wbh = (next >= 0) ? (const char*)(g_Wbh + (size_t)(next*8 + 4)*17408) : 0;
    const char* Wbl = (next >= 0) ? (const char*)(g_Wbl + (size_t)(next*8 + 4)*17408) : 0;

    if (tid < 128) { bb[tid] = b1[tid]; bb[128 + tid] = b2[tid]; }

    int m0 = (w & 1)*16, n0 = (w >> 1)*32;
    int rl = m0 + (lane >> 2);
    int cq = (lane & 3)*2;

    for (int t = blockIdx.x; t < NTN; t += gridDim.x) {
        int row0 = t*32;
        __syncthreads();   // prev tile fully done (A/W free); bb visible (1st iter)
        // load W5, split feat into A
        for (int i = tid; i < 2176; i += 256) {
            asm volatile("cp.async.cg.shared.global [%0], [%1], 16;"
                :: "r"(sb + 17408u + (unsigned)i*16u), "l"(W5h + (size_t)i*16) : "memory");
            asm volatile("cp.async.cg.shared.global [%0], [%1], 16;"
                :: "r"(sb + 52224u + (unsigned)i*16u), "l"(W5l + (size_t)i*16) : "memory");
        }
        asm volatile("cp.async.commit_group;" ::: "memory");
        #pragma unroll
        for (int q = 0; q < 4; q++) {
            int idx = tid + q*256;
            int r = idx >> 5, c4 = (idx & 31)*4;
            float4 v = make_float4(0.f,0.f,0.f,0.f);
            if (row0 + r < Nn) v = *(const float4*)(g_feat + (size_t)(row0 + r)*128 + c4);
            unsigned h[4], l[4];
            split_bf16(v.x, h[0], l[0]); split_bf16(v.y, h[1], l[1]);
            split_bf16(v.z, h[2], l[2]); split_bf16(v.w, h[3], l[3]);
            unsigned off = (unsigned)(r*136 + c4)*2u;
            *(uint2*)(smc + off)        = make_uint2(h[0]|(h[1]<<16), h[2]|(h[3]<<16));
            *(uint2*)(smc + 8704 + off) = make_uint2(l[0]|(l[1]<<16), l[2]|(l[3]<<16));
        }
        asm volatile("cp.async.wait_group 0;" ::: "memory");
        __syncthreads();

        // GEMM1: acc = feat @ W5
        float acc[4][4];
        #pragma unroll
        for (int i = 0; i < 4; i++)
            #pragma unroll
            for (int j = 0; j < 4; j++) acc[i][j] = 0.f;
        hmma_g16n32(sb, sb + 8704, sb + 17408, sb + 52224, m0, n0, lane, acc);
        __syncthreads();   // A + W reads done

        // load W6, split msum/deg into A (zero msum)
        for (int i = tid; i < 2176; i += 256) {
            asm volatile("cp.async.cg.shared.global [%0], [%1], 16;"
                :: "r"(sb + 17408u + (unsigned)i*16u), "l"(W6h + (size_t)i*16) : "memory");
            asm volatile("cp.async.cg.shared.global [%0], [%1], 16;"
                :: "r"(sb + 52224u + (unsigned)i*16u), "l"(W6l + (size_t)i*16) : "memory");
        }
        asm volatile("cp.async.commit_group;" ::: "memory");
        #pragma unroll
        for (int q = 0; q < 4; q++) {
            int idx = tid + q*256;
            int r = idx >> 5, c4 = (idx & 31)*4;
            float4 v = make_float4(0.f,0.f,0.f,0.f);
            if (row0 + r < Nn) {
                float* mp = g_msum + (size_t)(row0 + r)*128 + c4;
                v = *(const float4*)mp;
                *(float4*)mp = make_float4(0.f,0.f,0.f,0.f);
                float inv = 1.0f / fmaxf(g_deg[row0 + r], 1.0f);
                v.x *= inv; v.y *= inv; v.z *= inv; v.w *= inv;
            }
            unsigned h[4], l[4];
            split_bf16(v.x, h[0], l[0]); split_bf16(v.y, h[1], l[1]);
            split_bf16(v.z, h[2], l[2]); split_bf16(v.w, h[3], l[3]);
            unsigned off = (unsigned)(r*136 + c4)*2u;
            *(uint2*)(smc + off)        = make_uint2(h[0]|(h[1]<<16), h[2]|(h[3]<<16));
            *(uint2*)(smc + 8704 + off) = make_uint2(l[0]|(l[1]<<16), l[2]|(l[3]<<16));
        }
        asm volatile("cp.async.wait_group 0;" ::: "memory");
        __syncthreads();

        // GEMM2: acc += msum @ W6
        hmma_g16n32(sb, sb + 8704, sb + 17408, sb + 52224, m0, n0, lane, acc);
        __syncthreads();   // A + W reads done

        // load W7, split H = silu(acc + b1) into A
        for (int i = tid; i < 2176; i += 256) {
            asm volatile("cp.async.cg.shared.global [%0], [%1], 16;"
                :: "r"(sb + 17408u + (unsigned)i*16u), "l"(W7h + (size_t)i*16) : "memory");
            asm volatile("cp.async.cg.shared.global [%0], [%1], 16;"
                :: "r"(sb + 52224u + (unsigned)i*16u), "l"(W7l + (size_t)i*16) : "memory");
        }
        asm volatile("cp.async.commit_group;" ::: "memory");
        #pragma unroll
        for (int s = 0; s < 4; s++) {
            int col = n0 + s*8 + cq;
            float v00 = silu_f(acc[s][0] + bb[col]);
            float v01 = silu_f(acc[s][1] + bb[col+1]);
            float v10 = silu_f(acc[s][2] + bb[col]);
            float v11 = silu_f(acc[s][3] + bb[col+1]);
            unsigned h0, l0, h1, l1;
            split_bf16(v00, h0, l0); split_bf16(v01, h1, l1);
            *(unsigned*)(smc + (rl*136 + col)*2)        = h0 | (h1 << 16);
            *(unsigned*)(smc + 8704 + (rl*136 + col)*2) = l0 | (l1 << 16);
            split_bf16(v10, h0, l0); split_bf16(v11, h1, l1);
            *(unsigned*)(smc + ((rl+8)*136 + col)*2)        = h0 | (h1 << 16);
            *(unsigned*)(smc + 8704 + ((rl+8)*136 + col)*2) = l0 | (l1 << 16);
        }
        asm volatile("cp.async.wait_group 0;" ::: "memory");
        __syncthreads();

        // GEMM3: newfeat = H @ W7 (+ b2)
        #pragma unroll
        for (int i = 0; i < 4; i++)
            #pragma unroll
            for (int j = 0; j < 4; j++) acc[i][j] = 0.f;
        hmma_g16n32(sb, sb + 8704, sb + 17408, sb + 52224, m0, n0, lane, acc);
        #pragma unroll
        for (int s = 0; s < 4; s++) {
            int col = n0 + s*8 + cq;
            acc[s][0] += bb[128+col]; acc[s][1] += bb[128+col+1];
            acc[s][2] += bb[128+col]; acc[s][3] += bb[128+col+1];
            int ra = row0 + rl, rb = ra + 8;
            if (ra < Nn) *(float2*)(g_feat + (size_t)ra*128 + col) = make_float2(acc[s][0], acc[s][1]);
            if (rb < Nn) *(float2*)(g_feat + (size_t)rb*128 + col) = make_float2(acc[s][2], acc[s][3]);
        }
        if (next < 0) continue;

        __syncthreads();   // GEMM3 reads of A + W done block-wide
        // load Wa, split newfeat into A
        for (int i = tid; i < 2176; i += 256) {
            asm volatile("cp.async.cg.shared.global [%0], [%1], 16;"
                :: "r"(sb + 17408u + (unsigned)i*16u), "l"(Wah + (size_t)i*16) : "memory");
            asm volatile("cp.async.cg.shared.global [%0], [%1], 16;"
                :: "r"(sb + 52224u + (unsigned)i*16u), "l"(Wal + (size_t)i*16) : "memory");
        }
        asm volatile("cp.async.commit_group;" ::: "memory");
        #pragma unroll
        for (int s = 0; s < 4; s++) {
            int col = n0 + s*8 + cq;
            unsigned h0, l0, h1, l1;
            split_bf16(acc[s][0], h0, l0); split_bf16(acc[s][1], h1, l1);
            *(unsigned*)(smc + (rl*136 + col)*2)        = h0 | (h1 << 16);
            *(unsigned*)(smc + 8704 + (rl*136 + col)*2) = l0 | (l1 << 16);
            split_bf16(acc[s][2], h0, l0); split_bf16(acc[s][3], h1, l1);
            *(unsigned*)(smc + ((rl+8)*136 + col)*2)        = h0 | (h1 << 16);
            *(unsigned*)(smc + 8704 + ((rl+8)*136 + col)*2) = l0 | (l1 << 16);
        }
        asm volatile("cp.async.wait_group 0;" ::: "memory");
        __syncthreads();

        // GEMM4: featA = newfeat @ Wa
        #pragma unroll
        for (int i = 0; i < 4; i++)
            #pragma unroll
            for (int j = 0; j < 4; j++) acc[i][j] = 0.f;
        hmma_g16n32(sb, sb + 8704, sb + 17408, sb + 52224, m0, n0, lane, acc);
        #pragma unroll
        for (int s = 0; s < 4; s++) {
            int col = n0 + s*8 + cq;
            int ra = row0 + rl, rb = ra + 8;
            if (ra < Nn) *(float2*)(g_featA + (size_t)ra*128 + col) = make_float2(acc[s][0], acc[s][1]);
            if (rb < Nn) *(float2*)(g_featA + (size_t)rb*128 + col) = make_float2(acc[s][2], acc[s][3]);
        }
        __syncthreads();   // W reads done

        // load Wb
        for (int i = tid; i < 2176; i += 256) {
            asm volatile("cp.async.cg.shared.global [%0], [%1], 16;"
                :: "r"(sb + 17408u + (unsigned)i*16u), "l"(Wbh + (size_t)i*16) : "memory");
            asm volatile("cp.async.cg.shared.global [%0], [%1], 16;"
                :: "r"(sb + 52224u + (unsigned)i*16u), "l"(Wbl + (size_t)i*16) : "memory");
        }
        asm volatile("cp.async.commit_group;" ::: "memory");
        asm volatile("cp.async.wait_group 0;" ::: "memory");
        __syncthreads();

        // GEMM5: featB = newfeat @ Wb (A unchanged)
        #pragma unroll
        for (int i = 0; i < 4; i++)
            #pragma unroll
            for (int j = 0; j < 4; j++) acc[i][j] = 0.f;
        hmma_g16n32(sb, sb + 8704, sb + 17408, sb + 52224, m0, n0, lane, acc);
        #pragma unroll
        for (int s = 0; s < 4; s++) {
            int col = n0 + s*8 + cq;
            int ra = row0 + rl, rb = ra + 8;
            if (ra < Nn) *(float2*)(g_featB + (size_t)ra*128 + col) = make_float2(acc[s][0], acc[s][1]);
            if (rb < Nn) *(float2*)(g_featB + (size_t)rb*128 + col) = make_float2(acc[s][2], acc[s][3]);
        }
    }
}

// ============ FUSED edge kernel: 256 threads, 64-edge tiles, 2 blocks/SM (proven R16) ============
#define FU_SMEM 113152
__global__ void __launch_bounds__(256, 2)
edge_fused_mma(const float* __restrict__ bm2l,
               const float* __restrict__ Wm1tail, const float* __restrict__ bm1l,
               const float* __restrict__ bp1l, const float* __restrict__ Wp2l,
               const float* __restrict__ bp2l,
               const float* __restrict__ bs1l, const float* __restrict__ Ws2l,
               const float* __restrict__ bs2l, int layer) {
    extern __shared__ char smc[];
    unsigned sb = smem_u32(smc);
    float* scal = (float*)(smc + 104448);
    float* pd   = (float*)(smc + 104448);
    float* bh   = (float*)(smc + 106496);
    float* bhp  = (float*)(smc + 107008);
    float* bhs  = (float*)(smc + 107520);
    float* w2p  = (float*)(smc + 108032);
    float* w2s  = (float*)(smc + 108544);
    int* ridx   = (int*)(smc + 110080);
    int* cidx   = (int*)(smc + 110336);
    float* wtl  = (float*)(smc + 110592);
    int tid = threadIdx.x, w = tid >> 5, lane = tid & 31;

    const char* Wm2h = (const char*)(g_Wbh + (size_t)(layer*8 + 0)*17408);
    const char* Wm2l = (const char*)(g_Wbl + (size_t)(layer*8 + 0)*17408);
    const char* Wp1h = (const char*)(g_Wbh + (size_t)(layer*8 + 1)*17408);
    const char* Wp1l = (const char*)(g_Wbl + (size_t)(layer*8 + 1)*17408);
    const char* Ws1h = (const char*)(g_Wbh + (size_t)(layer*8 + 2)*17408);
    const char* Ws1l = (const char*)(g_Wbl + (size_t)(layer*8 + 2)*17408);

    if (tid < 128) {
        bh[tid] = bm2l[tid]; bhp[tid] = bp1l[tid]; bhs[tid] = bs1l[tid];
        w2p[tid] = Wp2l[tid];
        w2s[tid*3+0] = Ws2l[tid*3+0]; w2s[tid*3+1] = Ws2l[tid*3+1]; w2s[tid*3+2] = Ws2l[tid*3+2];
    }
    for (int i = tid; i < 640; i += 256)
        wtl[i] = (i < 512) ? Wm1tail[i] : bm1l[i - 512];

    int m0 = (w & 3)*16, n0 = (w >> 2)*64;
    int ngrp = w >> 2;
    int rl = m0 + (lane >> 2);

    for (int t = blockIdx.x; t < NT; t += gridDim.x) {
        int e0 = t*64;
        __syncthreads();
        for (int i = tid; i < 2176; i += 256) {
            asm volatile("cp.async.cg.shared.global [%0], [%1], 16;"
                :: "r"(sb + 34816u + (unsigned)i*16u), "l"(Wm2h + (size_t)i*16) : "memory");
            asm volatile("cp.async.cg.shared.global [%0], [%1], 16;"
                :: "r"(sb + 69632u + (unsigned)i*16u), "l"(Wm2l + (size_t)i*16) : "memory");
        }
        asm volatile("cp.async.commit_group;" ::: "memory");
        if (tid < 64) {
            int r = g_er[e0 + tid], c = g_ec[e0 + tid];
            ridx[tid] = r; cidx[tid] = c;
            float dp0 = g_pos[r*3+0] - g_pos[c*3+0];
            float dp1 = g_pos[r*3+1] - g_pos[c*3+1];
            float dp2 = g_pos[r*3+2] - g_pos[c*3+2];
            float ip2 = 0.f;
            #pragma unroll
            for (int q = 4; q < 9; q++) ip2 += g_sh[r*9+q]*g_sh[c*9+q];
            scal[tid*4+0] = dp0*dp0 + dp1*dp1 + dp2*dp2;
            scal[tid*4+1] = g_sh[r*9+0]*g_sh[c*9+0];
            scal[tid*4+2] = g_sh[r*9+1]*g_sh[c*9+1] + g_sh[r*9+2]*g_sh[c*9+2] + g_sh[r*9+3]*g_sh[c*9+3];
            scal[tid*4+3] = ip2;
        }
        __syncthreads();
        #pragma unroll
        for (int q = 0; q < 8; q++) {
            int idx = tid + q*256;
            int e = idx >> 5, c4 = (idx & 31)*4;
            int r = ridx[e], c = cidx[e];
            float4 fa = *(const float4*)(g_featA + (size_t)r*128 + c4);
            float4 fb = *(const float4*)(g_featB + (size_t)c*128 + c4);
            float d2 = scal[e*4+0], i0 = scal[e*4+1], i1 = scal[e*4+2], i2 = scal[e*4+3];
            float hv[4];
            hv[0] = silu_f(fa.x + fb.x + d2*wtl[c4+0] + i0*wtl[128+c4+0] + i1*wtl[256+c4+0] + i2*wtl[384+c4+0] + wtl[512+c4+0]);
            hv[1] = silu_f(fa.y + fb.y + d2*wtl[c4+1] + i0*wtl[128+c4+1] + i1*wtl[256+c4+1] + i2*wtl[384+c4+1] + wtl[512+c4+1]);
            hv[2] = silu_f(fa.z + fb.z + d2*wtl[c4+2] + i0*wtl[128+c4+2] + i1*wtl[256+c4+2] + i2*wtl[384+c4+2] + wtl[512+c4+2]);
            hv[3] = silu_f(fa.w + fb.w + d2*wtl[c4+3] + i0*wtl[128+c4+3] + i1*wtl[256+c4+3] + i2*wtl[384+c4+3] + wtl[512+c4+3]);
            unsigned h[4], l[4];
            #pragma unroll
            for (int j = 0; j < 4; j++) split_bf16(hv[j], h[j], l[j]);
            unsigned off = (unsigned)(e*136 + c4)*2u;
            *(uint2*)(smc + off)         = make_uint2(h[0]|(h[1]<<16), h[2]|(h[3]<<16));
            *(uint2*)(smc + 17408 + off) = make_uint2(l[0]|(l[1]<<16), l[2]|(l[3]<<16));
        }
        asm volatile("cp.async.wait_group 0;" ::: "memory");
        __syncthreads();

        float acc[8][4];
        #pragma unroll
        for (int i = 0; i < 8; i++)
            #pragma unroll
            for (int j = 0; j < 4; j++) acc[i][j] = 0.f;
        hmma_gemm(sb, sb + 17408, sb + 34816, sb + 69632, m0, n0, lane, acc);
        __syncthreads();

        for (int i = tid; i < 2176; i += 256) {
            asm volatile("cp.async.cg.shared.global [%0], [%1], 16;"
                :: "r"(sb + 34816u + (unsigned)i*16u), "l"(Wp1h + (size_t)i*16) : "memory");
            asm volatile("cp.async.cg.shared.global [%0], [%1], 16;"
                :: "r"(sb + 69632u + (unsigned)i*16u), "l"(Wp1l + (size_t)i*16) : "memory");
        }
        asm volatile("cp.async.commit_group;" ::: "memory");
        #pragma unroll
        for (int s = 0; s < 8; s++) {
            int col = n0 + s*8 + (lane & 3)*2;
            float v00 = silu_f(acc[s][0] + bh[col]);
            float v01 = silu_f(acc[s][1] + bh[col+1]);
            float v10 = silu_f(acc[s][2] + bh[col]);
            float v11 = silu_f(acc[s][3] + bh[col+1]);
            unsigned h0, l0, h1, l1;
            split_bf16(v00, h0, l0); split_bf16(v01, h1, l1);
            *(unsigned*)(smc + (rl*136 + col)*2)         = h0 | (h1 << 16);
            *(unsigned*)(smc + 17408 + (rl*136 + col)*2) = l0 | (l1 << 16);
            split_bf16(v10, h0, l0); split_bf16(v11, h1, l1);
            *(unsigned*)(smc + ((rl+8)*136 + col)*2)         = h0 | (h1 << 16);
            *(unsigned*)(smc + 17408 + ((rl+8)*136 + col)*2) = l0 | (l1 << 16);
        }
        asm volatile("cp.async.wait_group 0;" ::: "memory");
        __syncthreads();

        float accp[8][4];
        #pragma unroll
        for (int i = 0; i < 8; i++)
            #pragma unroll
            for (int j = 0; j < 4; j++) accp[i][j] = 0.f;
        hmma_gemm(sb, sb + 17408, sb + 34816, sb + 69632, m0, n0, lane, accp);
        __syncthreads();

        for (int i = tid; i < 2176; i += 256) {
            asm volatile("cp.async.cg.shared.global [%0], [%1], 16;"
                :: "r"(sb + 34816u + (unsigned)i*16u), "l"(Ws1h + (size_t)i*16) : "memory");
            asm volatile("cp.async.cg.shared.global [%0], [%1], 16;"
                :: "r"(sb + 69632u + (unsigned)i*16u), "l"(Ws1l + (size_t)i*16) : "memory");
        }
        asm volatile("cp.async.commit_group;" ::: "memory");
        {
            float pr0 = 0.f, pr1 = 0.f;
            #pragma unroll
            for (int s = 0; s < 8; s++) {
                int col = n0 + s*8 + (lane & 3)*2;
                pr0 = fmaf(silu_f(accp[s][0] + bhp[col]),   w2p[col],
                      fmaf(silu_f(accp[s][1] + bhp[col+1]), w2p[col+1], pr0));
                pr1 = fmaf(silu_f(accp[s][2] + bhp[col]),   w2p[col],
                      fmaf(silu_f(accp[s][3] + bhp[col+1]), w2p[col+1], pr1));
            }
            #pragma unroll
            for (int off = 1; off <= 2; off <<= 1) {
                pr0 += __shfl_xor_sync(0xffffffffu, pr0, off);
                pr1 += __shfl_xor_sync(0xffffffffu, pr1, off);
            }
            if ((lane & 3) == 0) {
                pd[ngrp*256 + rl*4 + 0] = pr0;
                pd[ngrp*256 + (rl+8)*4 + 0] = pr1;
            }
        }
        asm volatile("cp.async.wait_group 0;" ::: "memory");
        __syncthreads();

        float accs[8][4];
        #pragma unroll
        for (int i = 0; i < 8; i++)
            #pragma unroll
            for (int j = 0; j < 4; j++) accs[i][j] = 0.f;
        hmma_gemm(sb, sb + 17408, sb + 34816, sb + 69632, m0, n0, lane, accs);
        {
            float s0r0 = 0.f, s1r0 = 0.f, s2r0 = 0.f;
            float s0r1 = 0.f, s1r1 = 0.f, s2r1 = 0.f;
            #pragma unroll
            for (int s = 0; s < 8; s++) {
                int col = n0 + s*8 + (lane & 3)*2;
                float g00 = silu_f(accs[s][0] + bhs[col]);
                float g01 = silu_f(accs[s][1] + bhs[col+1]);
                float g10 = silu_f(accs[s][2] + bhs[col]);
                float g11 = silu_f(accs[s][3] + bhs[col+1]);
                s0r0 = fmaf(g00, w2s[col*3+0], fmaf(g01, w2s[(col+1)*3+0], s0r0));
                s1r0 = fmaf(g00, w2s[col*3+1], fmaf(g01, w2s[(col+1)*3+1], s1r0));
                s2r0 = fmaf(g00, w2s[col*3+2], fmaf(g01, w2s[(col+1)*3+2], s2r0));
                s0r1 = fmaf(g10, w2s[col*3+0], fmaf(g11, w2s[(col+1)*3+0], s0r1));
                s1r1 = fmaf(g10, w2s[col*3+1], fmaf(g11, w2s[(col+1)*3+1], s1r1));
                s2r1 = fmaf(g10, w2s[col*3+2], fmaf(g11, w2s[(col+1)*3+2], s2r1));
            }
            #pragma unroll
            for (int off = 1; off <= 2; off <<= 1) {
                s0r0 += __shfl_xor_sync(0xffffffffu, s0r0, off);
                s1r0 += __shfl_xor_sync(0xffffffffu, s1r0, off);
                s2r0 += __shfl_xor_sync(0xffffffffu, s2r0, off);
                s0r1 += __shfl_xor_sync(0xffffffffu, s0r1, off);
                s1r1 += __shfl_xor_sync(0xffffffffu, s1r1, off);
                s2r1 += __shfl_xor_sync(0xffffffffu, s2r1, off);
            }
            if ((lane & 3) == 0) {
                float* p0 = pd + ngrp*256 + rl*4;
                p0[1] = s0r0; p0[2] = s1r0; p0[3] = s2r0;
                float* p1 = pd + ngrp*256 + (rl+8)*4;
                p1[1] = s0r1; p1[2] = s1r1; p1[3] = s2r1;
            }
        }
        __syncthreads();
        if (tid < 64) {
            int r = ridx[tid], c = cidx[tid];
            float psc = pd[tid*4+0] + pd[256 + tid*4+0] + bp2l[0];
            float s0  = pd[tid*4+1] + pd[256 + tid*4+1] + bs2l[0];
            float s1  = pd[tid*4+2] + pd[256 + tid*4+2] + bs2l[1];
            float s2  = pd[tid*4+3] + pd[256 + tid*4+3] + bs2l[2];
            float dp0 = g_pos[r*3+0] - g_pos[c*3+0];
            float dp1 = g_pos[r*3+1] - g_pos[c*3+1];
            float dp2 = g_pos[r*3+2] - g_pos[c*3+2];
            atomicAdd(&g_psum[r*3+0], dp0*psc);
            atomicAdd(&g_psum[r*3+1], dp1*psc);
            atomicAdd(&g_psum[r*3+2], dp2*psc);
            #pragma unroll
            for (int q = 0; q < 9; q++) {
                float diff = g_sh[r*9+q] - g_sh[c*9+q];
                atomicAdd(&g_ssum[r*9+q], diff * ((q == 0) ? s0 : (q < 4) ? s1 : s2));
            }
        }
        {
            int c = tid & 127, seg = tid >> 7;
            int eb = seg*32;
            float agg = 0.f;
            int ar = ridx[eb];
            for (int e = eb; e < eb + 32; e++) {
                ush hi = *(const ush*)(smc + (e*136 + c)*2);
                ush lo = *(const ush*)(smc + 17408 + (e*136 + c)*2);
                float v = __bfloat162float(__ushort_as_bfloat16(hi))
                        + __bfloat162float(__ushort_as_bfloat16(lo));
                int r = ridx[e];
                if (r != ar) { atomicAdd(&g_msum[(size_t)ar*128 + c], agg); agg = v; ar = r; }
                else agg += v;
            }
            atomicAdd(&g_msum[(size_t)ar*128 + c], agg);
        }
    }
}

// posh also zeroes psum/ssum for the next layer
__global__ void posh_kernel() {
    int i = blockIdx.x*256 + threadIdx.x;
    if (i >= Nn) return;
    float inv = 1.0f / fmaxf(g_deg[i], 1.0f);
    #pragma unroll
    for (int q = 0; q < 3; q++) {
        g_pos[i*3+q] += g_psum[i*3+q]*inv;
        g_psum[i*3+q] = 0.0f;
    }
    #pragma unroll
    for (int q = 0; q < 9; q++) {
        g_sh[i*9+q] += g_ssum[i*9+q]*inv;
        g_ssum[i*9+q] = 0.0f;
    }
}
__global__ void pool_kernel(const int* __restrict__ batch) {
    int idx = blockIdx.x*256 + threadIdx.x;
    if (idx >= Nn*140) return;
    int i = idx / 140, c = idx % 140;
    float v;
    if (c < 128)      v = g_feat[(size_t)i*128 + c];
    else if (c < 131) v = g_pos[i*3 + (c - 128)];
    else              v = g_sh[i*9 + (c - 131)];
    atomicAdd(&g_pool[batch[i]*140 + c], v);
}
__global__ void pred_kernel(const float* __restrict__ Wpred, const float* __restrict__ bpred,
                            float* __restrict__ out) {
    int g = blockIdx.x, lane = threadIdx.x;
    float s = 0.f;
    for (int c = lane; c < 140; c += 32)
        s = fmaf(g_pool[g*140 + c], Wpred[c], s);
    #pragma unroll
    for (int off = 16; off > 0; off >>= 1)
        s += __shfl_xor_sync(0xffffffffu, s, off);
    if (lane == 0) out[g] = s + bpred[0];
}

extern "C" void kernel_launch(void* const* d_in, const int* in_sizes, int n_in,
                              void* d_out, int out_size) {
    const int*   atoms = (const int*)d_in[0];
    const int*   ei    = (const int*)d_in[1];
    const int*   batch = (const int*)d_in[2];
    const float* pos   = (const float*)d_in[3];
    const float* emb   = (const float*)d_in[4];
    const float* Wsi1  = (const float*)d_in[5];  const float* bsi1  = (const float*)d_in[6];
    const float* Wsi2  = (const float*)d_in[7];  const float* bsi2  = (const float*)d_in[8];
    const float* WsiC1 = (const float*)d_in[9];  const float* bsiC1 = (const float*)d_in[10];
    const float* WsiC2 = (const float*)d_in[11]; const float* bsiC2 = (const float*)d_in[12];
    const float* Wm1   = (const float*)d_in[13]; const float* bm1   = (const float*)d_in[14];
    const float* Wm2   = (const float*)d_in[15]; const float* bm2   = (const float*)d_in[16];
    const float* Wp1   = (const float*)d_in[17]; const float* bp1   = (const float*)d_in[18];
    const float* Wp2   = (const float*)d_in[19]; const float* bp2   = (const float*)d_in[20];
    const float* Wn1   = (const float*)d_in[21]; const float* bn1   = (const float*)d_in[22];
    const float* Wn2   = (const float*)d_in[23]; const float* bn2   = (const float*)d_in[24];
    const float* Ws1   = (const float*)d_in[25]; const float* bs1   = (const float*)d_in[26];
    const float* Ws2   = (const float*)d_in[27]; const float* bs2   = (const float*)d_in[28];
    const float* Wpred = (const float*)d_in[29]; const float* bpred = (const float*)d_in[30];
    float* out = (float*)d_out;

    cudaFuncSetAttribute(featab_mma, cudaFuncAttributeMaxDynamicSharedMemorySize, FABM_SMEM);
    cudaFuncSetAttribute(nodeup_mma2, cudaFuncAttributeMaxDynamicSharedMemorySize, NU2_SMEM);
    cudaFuncSetAttribute(edge_fused_mma, cudaFuncAttributeMaxDynamicSharedMemorySize, FU_SMEM);

    void *p_msum, *p_psum, *p_ssum, *p_deg, *p_com, *p_cnt, *p_pool, *p_pos, *p_cur;
    cudaGetSymbolAddress(&p_msum, g_msum);
    cudaGetSymbolAddress(&p_psum, g_psum);
    cudaGetSymbolAddress(&p_ssum, g_ssum);
    cudaGetSymbolAddress(&p_deg,  g_deg);
    cudaGetSymbolAddress(&p_com,  g_com);
    cudaGetSymbolAddress(&p_cnt,  g_cnt);
    cudaGetSymbolAddress(&p_pool, g_pool);
    cudaGetSymbolAddress(&p_pos,  g_pos);
    cudaGetSymbolAddress(&p_cur,  g_cursor);

    cudaMemsetAsync(p_deg,  0, Nn*4, 0);
    cudaMemsetAsync(p_com,  0, Gg*3*4, 0);
    cudaMemsetAsync(p_cnt,  0, Gg*4, 0);
    cudaMemsetAsync(p_ssum, 0, Nn*9*4, 0);
    cudaMemsetAsync(p_psum, 0, Nn*3*4, 0);
    cudaMemsetAsync(p_msum, 0, (size_t)Nn*128*4, 0);
    cudaMemsetAsync(p_pool, 0, Gg*140*4, 0);
    cudaMemsetAsync(p_cur,  0, Nn*4, 0);
    cudaMemcpyAsync(p_pos, pos, Nn*3*4, cudaMemcpyDeviceToDevice, 0);

    wprep_kernel<<<40, 256>>>(Wm2, Wp1, Ws1, Wm1, Wn1, Wn2);
    node_init_kernel<<<(Nn*128)/256, 256>>>(atoms, emb);
    com_kernel<<<(Nn + 255)/256, 256>>>(batch);
    deg_kernel<<<(Ee + 255)/256, 256>>>(ei);
    scan_kernel<<<1, 256>>>();
    sortscatter_kernel<<<(Ee + 255)/256, 256>>>(ei);
    vocab_kernel<<<10, 128>>>(emb, Wsi1, WsiC1, bsiC1, WsiC2, bsiC2);
    edge_init_kernel<<<Ee/8, 256>>>(atoms, Wsi1, bsi1, Wsi2, bsi2);
    sh_init_kernel<<<(Nn + 255)/256, 256>>>(atoms, batch);

    int gridNM = (Nn + 127)/128;   // 79 (featab layer 0)

    featab_mma<<<gridNM, 512, FABM_SMEM>>>(0);

    for (int l = 0; l < Ll; l++) {
        edge_fused_mma<<<296, 256, FU_SMEM>>>(
            bm2 + l*128,
            Wm1 + ((size_t)l*260 + 256)*128, bm1 + l*128,
            bp1 + l*128, Wp2 + l*128, bp2 + l,
            bs1 + l*128, Ws2 + l*384, bs2 + l*3, l);

        posh_kernel<<<(Nn + 255)/256, 256>>>();

        nodeup_mma2<<<296, 256, NU2_SMEM>>>(bn1 + l*128, bn2 + l*128, l,
                                            (l + 1 < Ll) ? (l + 1) : -1);
    }

    pool_kernel<<<(Nn*140 + 255)/256, 256>>>(batch);
    pred_kernel<<<Gg, 32>>>(Wpred, bpred, out);
}